// round 12
// baseline (speedup 1.0000x reference)
#include <cuda_runtime.h>
#include <cuda_fp16.h>
#include <cstdint>

#define B_   16
#define N_   1024
#define E_   1024
#define H_   16
#define D_   64
#define M_   (B_ * N_)        // 16384
#define QKV_N (3 * E_)        // 3072
#define KT_   (E_ / 64)       // 16 k-iters of 64

// ---------------------------------------------------------------------------
// Scratch (__device__ globals; no allocations)
// ---------------------------------------------------------------------------
static __device__ __align__(1024) __half g_q16 [(size_t)B_ * H_ * N_ * D_];
static __device__ __align__(1024) __half g_k16 [(size_t)B_ * H_ * N_ * D_];
static __device__ __align__(1024) __half g_vt16[(size_t)B_ * H_ * D_ * N_];  // V^T [B,H,D,N]
static __device__ __align__(1024) __half g_a16 [(size_t)M_ * E_];    // x, then attn out
static __device__ __align__(1024) __half g_wq16[(size_t)QKV_N * E_]; // Wqkv^T (n-major)
static __device__ __align__(1024) __half g_wp16[(size_t)E_ * E_];    // Wproj^T (n-major)

// ---------------------------------------------------------------------------
// helpers
// ---------------------------------------------------------------------------
__device__ __forceinline__ uint32_t smem_u32(const void* p) {
    uint32_t a;
    asm("{ .reg .u64 t; cvta.to.shared.u64 t, %1; cvt.u32.u64 %0, t; }"
        : "=r"(a) : "l"(p));
    return a;
}
__device__ __forceinline__ void cp_async16(uint32_t dst, const void* src) {
    asm volatile("cp.async.cg.shared.global [%0], [%1], 16;" :: "r"(dst), "l"(src));
}
__device__ __forceinline__ void cp_commit() {
    asm volatile("cp.async.commit_group;" ::: "memory");
}
__device__ __forceinline__ void ldmatrix_x4(uint32_t* d, uint32_t addr) {
    asm volatile("ldmatrix.sync.aligned.m8n8.x4.shared.b16 {%0,%1,%2,%3}, [%4];"
                 : "=r"(d[0]), "=r"(d[1]), "=r"(d[2]), "=r"(d[3]) : "r"(addr));
}
__device__ __forceinline__ void mma16816(float* c, const uint32_t* a,
                                         uint32_t b0, uint32_t b1) {
    asm volatile(
        "mma.sync.aligned.m16n8k16.row.col.f32.f16.f16.f32 "
        "{%0,%1,%2,%3}, {%4,%5,%6,%7}, {%8,%9}, {%0,%1,%2,%3};"
        : "+f"(c[0]), "+f"(c[1]), "+f"(c[2]), "+f"(c[3])
        : "r"(a[0]), "r"(a[1]), "r"(a[2]), "r"(a[3]), "r"(b0), "r"(b1));
}
__device__ __forceinline__ uint32_t packh2(float x, float y) {
    __half2 h = __floats2half2_rn(x, y);
    return *reinterpret_cast<uint32_t*>(&h);
}
#define MBAR_INIT(addr, cnt) \
    asm volatile("mbarrier.init.shared.b64 [%0], %1;" :: "r"(addr), "r"(cnt) : "memory")
#define MBAR_ARRIVE(addr) \
    asm volatile("mbarrier.arrive.shared.b64 _, [%0];" :: "r"(addr) : "memory")
#define MBAR_ARRIVE_CPASYNC(addr) \
    asm volatile("cp.async.mbarrier.arrive.noinc.shared.b64 [%0];" :: "r"(addr) : "memory")
#define MBAR_WAIT(addr, parity) do {                                          \
    asm volatile(                                                             \
        "{\n\t.reg .pred P1;\n\t"                                             \
        "WAIT_%=:\n\t"                                                        \
        "mbarrier.try_wait.parity.acquire.cta.shared::cta.b64 P1, [%0], %1, 0x989680;\n\t" \
        "@P1 bra.uni DONE_%=;\n\t"                                            \
        "bra.uni WAIT_%=;\n\t"                                                \
        "DONE_%=:\n\t}"                                                       \
        :: "r"(addr), "r"(parity) : "memory");                                \
} while (0)

// ---------------------------------------------------------------------------
// Fused conversion kernel (single launch):
//   blocks [0, 16384)         : x fp32 -> g_a16 fp16 (one row each)
//   blocks [16384, 16384+768) : Wq transpose tiles (16 kblk x 48 nblk)
//   blocks [+768, +768+256)   : Wp transpose tiles (16 kblk x 16 nblk)
// ---------------------------------------------------------------------------
__global__ __launch_bounds__(256) void conv_all_kernel(
    const float* __restrict__ x, const float* __restrict__ Wq,
    const float* __restrict__ Wp)
{
    __shared__ float tile[64][65];
    const int tid = threadIdx.x;
    const int bidx = blockIdx.x;

    if (bidx < M_) {
        const int k4 = tid << 2;
        float4 v = *(const float4*)(x + (size_t)bidx * E_ + k4);
        uint2 o;
        o.x = packh2(v.x, v.y);
        o.y = packh2(v.z, v.w);
        *(uint2*)&g_a16[(size_t)bidx * E_ + k4] = o;
        return;
    }

    const float* W;
    __half* dst;
    int Ncols, t;
    if (bidx < M_ + 768) {
        t = bidx - M_;       W = Wq; dst = g_wq16; Ncols = QKV_N;
    } else {
        t = bidx - M_ - 768; W = Wp; dst = g_wp16; Ncols = E_;
    }
    const int k0 = (t & 15) * 64;
    const int n0 = (t >> 4) * 64;

    const int lr = tid >> 6;
    const int lc = tid & 63;
#pragma unroll
    for (int i = 0; i < 16; i++) {
        const int r = lr + i * 4;
        tile[r][lc] = W[(size_t)(k0 + r) * Ncols + n0 + lc];
    }
    __syncthreads();

    const int nl = tid >> 2;
    const int kc = (tid & 3) << 4;
#pragma unroll
    for (int j = 0; j < 16; j += 4) {
        uint2 o;
        o.x = packh2(tile[kc + j][nl],     tile[kc + j + 1][nl]);
        o.y = packh2(tile[kc + j + 2][nl], tile[kc + j + 3][nl]);
        *(uint2*)&dst[(size_t)(n0 + nl) * E_ + k0 + kc + j] = o;
    }
}

// ---------------------------------------------------------------------------
// fp16 HMMA GEMM, producer/consumer mbarrier pipeline, TWO producer warps
// (warp 4 -> A tile, warp 5 -> B tile) to halve cp.async issue latency.
// Warps 0-3: consumers (64x64 tiles, reg-dbuf fragments). 3-stage ring.
// smem: [0,48) barriers (full[s]@s*16 cnt=64, empty[s]@s*16+8 cnt=128),
// stages @1024 (32KB each: A @0, B @16384).
// mode 0: write Q/K fp16 [B,H,N,D] + V^T fp16 [B,H,D,N]; mode 1: fp32 out.
// ---------------------------------------------------------------------------
#define GEMM_SMEM (1024 + 3 * 32768)

__global__ __launch_bounds__(192) void hgemm_kernel(
    const float* __restrict__ bias, float* __restrict__ out, int mode)
{
    extern __shared__ char smem[];
    const uint32_t sb = smem_u32(smem);
    const __half* A  = g_a16;
    const __half* Bt = (mode == 0) ? g_wq16 : g_wp16;

    const int tid  = threadIdx.x;
    const int lane = tid & 31, wid = tid >> 5;
    const int m0 = blockIdx.y * 128, n0 = blockIdx.x * 128;

    if (tid == 0) {
#pragma unroll
        for (int s = 0; s < 3; s++) {
            MBAR_INIT(sb + s * 16, 64);       // full: 2 producer warps
            MBAR_INIT(sb + s * 16 + 8, 128);  // empty: 128 consumer threads
        }
    }
    __syncthreads();   // the ONLY block-wide barrier

    if (wid >= 4) {
        // ------------------- producer warps (4: A, 5: B) -------------------
        const int isB = wid - 4;            // 0 -> A, 1 -> B
        const char* base = isB
            ? (const char*)(Bt + (size_t)n0 * E_)
            : (const char*)(A  + (size_t)m0 * E_);
        const uint32_t soffBase = isB ? 16384u : 0u;
        for (int t = 0; t < KT_; t++) {
            const int s = t % 3;
            if (t >= 3) MBAR_WAIT(sb + s * 16 + 8, ((t - 3) / 3) & 1);
            const uint32_t sa = sb + 1024 + s * 32768 + soffBase;
            const char* src = base + t * 128;
#pragma unroll
            for (int i = 0; i < 32; i++) {
                const int u = i * 32 + lane;
                const int r = u >> 3, c = u & 7;
                cp_async16(sa + r * 128 + ((c ^ (r & 7)) << 4),
                           src + (size_t)r * (E_ * 2) + c * 16);
            }
            MBAR_ARRIVE_CPASYNC(sb + s * 16);
        }
        return;
    }

    // --------------------------- consumer warps ---------------------------
    const int warp_m = wid & 1, warp_n = wid >> 1;

    float acc[4][8][4];
#pragma unroll
    for (int i = 0; i < 4; i++)
#pragma unroll
        for (int j = 0; j < 8; j++)
#pragma unroll
            for (int r = 0; r < 4; r++) acc[i][j][r] = 0.f;

    const int lane15 = lane & 15, lhalf = lane >> 4;
    const int ra  = warp_m * 64 + lane15;
    const int rbw = warp_n * 64 + lane15;

    for (int kt = 0; kt < KT_; kt++) {
        const int s = kt % 3;
        MBAR_WAIT(sb + s * 16, (kt / 3) & 1);   // full[s]

        const uint32_t sa  = sb + 1024 + s * 32768;
        const uint32_t sbB = sa + 16384;

        uint32_t afr[2][4][4], bfr[2][4][4];
        {
            const int kc = lhalf;
#pragma unroll
            for (int mi = 0; mi < 4; mi++) {
                const int r = ra + mi * 16;
                ldmatrix_x4(afr[0][mi], sa + r * 128 + ((kc ^ (r & 7)) << 4));
            }
#pragma unroll
            for (int ng = 0; ng < 4; ng++) {
                const int r = rbw + ng * 16;
                ldmatrix_x4(bfr[0][ng], sbB + r * 128 + ((kc ^ (r & 7)) << 4));
            }
        }
#pragma unroll
        for (int kk = 0; kk < 4; kk++) {
            const int cur = kk & 1, nxt = cur ^ 1;
            if (kk < 3) {
                const int kc = (kk + 1) * 2 + lhalf;
#pragma unroll
                for (int mi = 0; mi < 4; mi++) {
                    const int r = ra + mi * 16;
                    ldmatrix_x4(afr[nxt][mi], sa + r * 128 + ((kc ^ (r & 7)) << 4));
                }
#pragma unroll
                for (int ng = 0; ng < 4; ng++) {
                    const int r = rbw + ng * 16;
                    ldmatrix_x4(bfr[nxt][ng], sbB + r * 128 + ((kc ^ (r & 7)) << 4));
                }
            }
#pragma unroll
            for (int mi = 0; mi < 4; mi++)
#pragma unroll
                for (int nj = 0; nj < 8; nj++)
                    mma16816(acc[mi][nj], afr[cur][mi],
                             bfr[cur][nj >> 1][nj & 1],
                             bfr[cur][nj >> 1][(nj & 1) + 2]);
        }
        MBAR_ARRIVE(sb + s * 16 + 8);           // empty[s]
    }

    // Epilogue (consumers only)
    const int mrow = m0 + warp_m * 64 + (lane >> 2);
    const int ncb  = n0 + warp_n * 64 + (lane & 3) * 2;
#pragma unroll
    for (int mi = 0; mi < 4; mi++) {
#pragma unroll
        for (int nj = 0; nj < 8; nj++) {
            const int c  = ncb + nj * 8;
            const float b0 = bias[c], b1 = bias[c + 1];
            const int r0 = mrow + mi * 16;
            const float v00 = acc[mi][nj][0] + b0, v01 = acc[mi][nj][1] + b1;
            const float v10 = acc[mi][nj][2] + b0, v11 = acc[mi][nj][3] + b1;
            if (mode == 1) {
                float2 p0; p0.x = v00; p0.y = v01;
                float2 p1; p1.x = v10; p1.y = v11;
                *(float2*)&out[(size_t)r0 * E_ + c] = p0;
                *(float2*)&out[(size_t)(r0 + 8) * E_ + c] = p1;
                continue;
            }
            const int sec = c >> 10, e = c & 1023;
            const int hh = e >> 6, dd = e & 63;
            const int bb = r0 >> 10, nn = r0 & 1023;
            if (sec <= 1) {
                __half* dq = sec == 0 ? g_q16 : g_k16;
                const size_t i0 = (((size_t)bb * H_ + hh) * N_ + nn) * D_ + dd;
                *(uint32_t*)&dq[i0]          = packh2(v00, v01);
                *(uint32_t*)&dq[i0 + 8 * D_] = packh2(v10, v11);
            } else {
                const size_t i00 = (((size_t)bb * H_ + hh) * D_ + dd) * N_ + nn;
                g_vt16[i00]          = __float2half_rn(v00);
                g_vt16[i00 + N_]     = __float2half_rn(v01);
                g_vt16[i00 + 8]      = __float2half_rn(v10);
                g_vt16[i00 + N_ + 8] = __float2half_rn(v11);
            }
        }
    }
}

// ---------------------------------------------------------------------------
// Flash attention, fp16 HMMA — reverted to the R10 cooperative version
// (fastest measured): 128 q-rows per CTA (8 warps), 2-stage cp.async pipeline,
// loads spread across all 256 threads.
// ---------------------------------------------------------------------------
#define ATT_SMEM (2 * 16384)

__device__ __forceinline__ void att_load_tile(
    uint32_t st, int kv0, const __half* k16, const __half* vt16, int tid)
{
#pragma unroll
    for (int i = 0; i < 2; i++) {
        const int u = i * 256 + tid;
        const int r = u >> 3, c = u & 7;
        const uint32_t soff = r * 128 + ((c ^ (r & 7)) << 4);
        cp_async16(st + soff,        (const char*)k16  + (size_t)(kv0 + r) * 128 + c * 16);
        cp_async16(st + 8192 + soff, (const char*)vt16 + (size_t)r * 2048 + kv0 * 2 + c * 16);
    }
    cp_commit();
}

__global__ __launch_bounds__(256) void attn_kernel()
{
    extern __shared__ char smem[];
    const uint32_t sb = smem_u32(smem);

    const int tid = threadIdx.x;
    const int lane = tid & 31, w = tid >> 5;
    const int lane15 = lane & 15, lhalf = lane >> 4;
    const int q0 = blockIdx.x * 128;
    const int h  = blockIdx.y;
    const int b  = blockIdx.z;

    const size_t hb = (size_t)(b * H_ + h) * (N_ * D_);
    const __half* q16  = g_q16  + hb;
    const __half* k16  = g_k16  + hb;
    const __half* vt16 = g_vt16 + hb;

#pragma unroll
    for (int i = 0; i < 4; i++) {
        const int u = i * 256 + tid;
        const int r = u >> 3, c = u & 7;
        cp_async16(sb + r * 128 + ((c ^ (r & 7)) << 4),
                   (const char*)q16 + (size_t)(q0 + r) * 128 + c * 16);
    }
    cp_commit();
    asm volatile("cp.async.wait_group 0;" ::: "memory");
    __syncthreads();

    uint32_t qf[4][4];
    {
        const int r = w * 16 + lane15;
#pragma unroll
        for (int t = 0; t < 4; t++)
            ldmatrix_x4(qf[t], sb + r * 128 + (((t * 2 + lhalf) ^ (r & 7)) << 4));
    }
    __syncthreads();

    float mstate[2] = {-1e30f, -1e30f};
    float lstate[2] = {0.f, 0.f};
    float oacc[8][4];
#pragma unroll
    for (int j = 0; j < 8; j++)
#pragma unroll
        for (int r = 0; r < 4; r++) oacc[j][r] = 0.f;

    const float cexp = 0.18033688f;   // D^-0.5 * log2(e)

    att_load_tile(sb, 0, k16, vt16, tid);
    att_load_tile(sb + 16384, 64, k16, vt16, tid);

    for (int t = 0; t < 16; t++) {
        asm volatile("cp.async.wait_group 1;" ::: "memory");
        __syncthreads();
        const uint32_t stK = sb + (t & 1) * 16384;
        const uint32_t stV = stK + 8192;

        float sacc[8][4];
#pragma unroll
        for (int j = 0; j < 8; j++)
#pragma unroll
            for (int r = 0; r < 4; r++) sacc[j][r] = 0.f;

#pragma unroll
        for (int kvg = 0; kvg < 4; kvg++) {
            const int rb = kvg * 16 + lane15;
#pragma unroll
            for (int kk = 0; kk < 4; kk++) {
                uint32_t bf[4];
                ldmatrix_x4(bf, stK + rb * 128 + (((kk * 2 + lhalf) ^ (rb & 7)) << 4));
                mma16816(sacc[2 * kvg],     qf[kk], bf[0], bf[2]);
                mma16816(sacc[2 * kvg + 1], qf[kk], bf[1], bf[3]);
            }
        }

#pragma unroll
        for (int rr = 0; rr < 2; rr++) {
            float mx = -1e30f;
#pragma unroll
            for (int j = 0; j < 8; j++)
                mx = fmaxf(mx, fmaxf(sacc[j][rr * 2], sacc[j][rr * 2 + 1]));
            mx = fmaxf(mx, __shfl_xor_sync(0xffffffffu, mx, 1));
            mx = fmaxf(mx, __shfl_xor_sync(0xffffffffu, mx, 2));
            const float mnew  = fmaxf(mstate[rr], mx);
            const float alpha = exp2f((mstate[rr] - mnew) * cexp);
            mstate[rr] = mnew;
            float rs = 0.f;
#pragma unroll
            for (int j = 0; j < 8; j++) {
                const float p0 = exp2f((sacc[j][rr * 2]     - mnew) * cexp);
                const float p1 = exp2f((sacc[j][rr * 2 + 1] - mnew) * cexp);
                sacc[j][rr * 2] = p0; sacc[j][rr * 2 + 1] = p1;
                rs += p0 + p1;
            }
            rs += __shfl_xor_sync(0xffffffffu, rs, 1);
            rs += __shfl_xor_sync(0xffffffffu, rs, 2);
            lstate[rr] = lstate[rr] * alpha + rs;
#pragma unroll
            for (int j = 0; j < 8; j++) {
                oacc[j][rr * 2]     *= alpha;
                oacc[j][rr * 2 + 1] *= alpha;
            }
        }

        uint32_t pf[4][4];
#pragma unroll
        for (int kk = 0; kk < 4; kk++) {
#pragma unroll
            for (int q = 0; q < 4; q++) {
                const int tile = 2 * kk + (q >> 1);
                const int ri   = (q & 1) * 2;
                pf[kk][q] = packh2(sacc[tile][ri], sacc[tile][ri + 1]);
            }
        }

#pragma unroll
        for (int dg = 0; dg < 4; dg++) {
            const int rb = dg * 16 + lane15;
#pragma unroll
            for (int kk = 0; kk < 4; kk++) {
                uint32_t bf[4];
                ldmatrix_x4(bf, stV + rb * 128 + (((kk * 2 + lhalf) ^ (rb & 7)) << 4));
                mma16816(oacc[2 * dg],     pf[kk], bf[0], bf[2]);
                mma16816(oacc[2 * dg + 1], pf[kk], bf[1], bf[3]);
            }
        }

        __syncthreads();
        if (t + 2 < 16)
            att_load_tile(sb + (t & 1) * 16384, (t + 2) * 64, k16, vt16, tid);
        else
            cp_commit();
    }

    const float inv0 = 1.f / lstate[0];
    const float inv1 = 1.f / lstate[1];
    const int qrow = q0 + w * 16 + (lane >> 2);
    const size_t m0r = (size_t)(b * N_ + qrow) * E_;
    const size_t m1r = m0r + (size_t)8 * E_;
    const int colb = h * 64 + 2 * (lane & 3);
#pragma unroll
    for (int j = 0; j < 8; j++) {
        const int col = colb + 8 * j;
        *(uint32_t*)&g_a16[m0r + col] = packh2(oacc[j][0] * inv0, oacc[j][1] * inv0);
        *(uint32_t*)&g_a16[m1r + col] = packh2(oacc[j][2] * inv1, oacc[j][3] * inv1);
    }
}

// ---------------------------------------------------------------------------
extern "C" void kernel_launch(void* const* d_in, const int* in_sizes, int n_in,
                              void* d_out, int out_size)
{
    const float* x  = (const float*)d_in[0];
    const float* Wq = (const float*)d_in[1];
    const float* bq = (const float*)d_in[2];
    const float* Wp = (const float*)d_in[3];
    const float* bp = (const float*)d_in[4];
    float* out = (float*)d_out;

    cudaFuncSetAttribute(hgemm_kernel,
                         cudaFuncAttributeMaxDynamicSharedMemorySize, GEMM_SMEM);
    cudaFuncSetAttribute(attn_kernel,
                         cudaFuncAttributeMaxDynamicSharedMemorySize, ATT_SMEM);

    conv_all_kernel<<<M_ + 768 + 256, 256>>>(x, Wq, Wp);

    hgemm_kernel<<<dim3(QKV_N / 128, M_ / 128), 192, GEMM_SMEM>>>(bq, out, 0);

    attn_kernel<<<dim3(N_ / 128, H_, B_), 256, ATT_SMEM>>>();

    hgemm_kernel<<<dim3(E_ / 128, M_ / 128), 192, GEMM_SMEM>>>(bp, out, 1);
}

// round 13
// speedup vs baseline: 1.2523x; 1.2523x over previous
#include <cuda_runtime.h>
#include <cuda_fp16.h>
#include <cstdint>

#define B_   16
#define N_   1024
#define E_   1024
#define H_   16
#define D_   64
#define M_   (B_ * N_)        // 16384
#define QKV_N (3 * E_)        // 3072
#define KT_   (E_ / 64)       // 16 k-iters of 64

// ---------------------------------------------------------------------------
// Scratch (__device__ globals; no allocations)
// ---------------------------------------------------------------------------
static __device__ __align__(1024) __half g_q16 [(size_t)B_ * H_ * N_ * D_];
static __device__ __align__(1024) __half g_k16 [(size_t)B_ * H_ * N_ * D_];
static __device__ __align__(1024) __half g_vt16[(size_t)B_ * H_ * D_ * N_];  // V^T [B,H,D,N]
static __device__ __align__(1024) __half g_a16 [(size_t)M_ * E_];    // x, then attn out
static __device__ __align__(1024) __half g_wq16[(size_t)QKV_N * E_]; // Wqkv^T (n-major)
static __device__ __align__(1024) __half g_wp16[(size_t)E_ * E_];    // Wproj^T (n-major)

// ---------------------------------------------------------------------------
// helpers
// ---------------------------------------------------------------------------
__device__ __forceinline__ uint32_t smem_u32(const void* p) {
    uint32_t a;
    asm("{ .reg .u64 t; cvta.to.shared.u64 t, %1; cvt.u32.u64 %0, t; }"
        : "=r"(a) : "l"(p));
    return a;
}
__device__ __forceinline__ void cp_async16(uint32_t dst, const void* src) {
    asm volatile("cp.async.cg.shared.global [%0], [%1], 16;" :: "r"(dst), "l"(src));
}
__device__ __forceinline__ void cp_commit() {
    asm volatile("cp.async.commit_group;" ::: "memory");
}
__device__ __forceinline__ void ldmatrix_x4(uint32_t* d, uint32_t addr) {
    asm volatile("ldmatrix.sync.aligned.m8n8.x4.shared.b16 {%0,%1,%2,%3}, [%4];"
                 : "=r"(d[0]), "=r"(d[1]), "=r"(d[2]), "=r"(d[3]) : "r"(addr));
}
__device__ __forceinline__ void mma16816(float* c, const uint32_t* a,
                                         uint32_t b0, uint32_t b1) {
    asm volatile(
        "mma.sync.aligned.m16n8k16.row.col.f32.f16.f16.f32 "
        "{%0,%1,%2,%3}, {%4,%5,%6,%7}, {%8,%9}, {%0,%1,%2,%3};"
        : "+f"(c[0]), "+f"(c[1]), "+f"(c[2]), "+f"(c[3])
        : "r"(a[0]), "r"(a[1]), "r"(a[2]), "r"(a[3]), "r"(b0), "r"(b1));
}
__device__ __forceinline__ uint32_t packh2(float x, float y) {
    __half2 h = __floats2half2_rn(x, y);
    return *reinterpret_cast<uint32_t*>(&h);
}
#define MBAR_INIT(addr, cnt) \
    asm volatile("mbarrier.init.shared.b64 [%0], %1;" :: "r"(addr), "r"(cnt) : "memory")
#define MBAR_ARRIVE(addr) \
    asm volatile("mbarrier.arrive.shared.b64 _, [%0];" :: "r"(addr) : "memory")
#define MBAR_ARRIVE_CPASYNC(addr) \
    asm volatile("cp.async.mbarrier.arrive.noinc.shared.b64 [%0];" :: "r"(addr) : "memory")
#define MBAR_WAIT(addr, parity) do {                                          \
    asm volatile(                                                             \
        "{\n\t.reg .pred P1;\n\t"                                             \
        "WAIT_%=:\n\t"                                                        \
        "mbarrier.try_wait.parity.acquire.cta.shared::cta.b64 P1, [%0], %1, 0x989680;\n\t" \
        "@P1 bra.uni DONE_%=;\n\t"                                            \
        "bra.uni WAIT_%=;\n\t"                                                \
        "DONE_%=:\n\t}"                                                       \
        :: "r"(addr), "r"(parity) : "memory");                                \
} while (0)

// ---------------------------------------------------------------------------
// Fused conversion kernel (single launch):
//   blocks [0, 16384)         : x fp32 -> g_a16 fp16 (one row each)
//   blocks [16384, 16384+768) : Wq transpose tiles (16 kblk x 48 nblk)
//   blocks [+768, +768+256)   : Wp transpose tiles (16 kblk x 16 nblk)
// ---------------------------------------------------------------------------
__global__ __launch_bounds__(256) void conv_all_kernel(
    const float* __restrict__ x, const float* __restrict__ Wq,
    const float* __restrict__ Wp)
{
    __shared__ float tile[64][65];
    const int tid = threadIdx.x;
    const int bidx = blockIdx.x;

    if (bidx < M_) {
        const int k4 = tid << 2;
        float4 v = *(const float4*)(x + (size_t)bidx * E_ + k4);
        uint2 o;
        o.x = packh2(v.x, v.y);
        o.y = packh2(v.z, v.w);
        *(uint2*)&g_a16[(size_t)bidx * E_ + k4] = o;
        return;
    }

    const float* W;
    __half* dst;
    int Ncols, t;
    if (bidx < M_ + 768) {
        t = bidx - M_;       W = Wq; dst = g_wq16; Ncols = QKV_N;
    } else {
        t = bidx - M_ - 768; W = Wp; dst = g_wp16; Ncols = E_;
    }
    const int k0 = (t & 15) * 64;
    const int n0 = (t >> 4) * 64;

    const int lr = tid >> 6;
    const int lc = tid & 63;
#pragma unroll
    for (int i = 0; i < 16; i++) {
        const int r = lr + i * 4;
        tile[r][lc] = W[(size_t)(k0 + r) * Ncols + n0 + lc];
    }
    __syncthreads();

    const int nl = tid >> 2;
    const int kc = (tid & 3) << 4;
#pragma unroll
    for (int j = 0; j < 16; j += 4) {
        uint2 o;
        o.x = packh2(tile[kc + j][nl],     tile[kc + j + 1][nl]);
        o.y = packh2(tile[kc + j + 2][nl], tile[kc + j + 3][nl]);
        *(uint2*)&dst[(size_t)(n0 + nl) * E_ + k0 + kc + j] = o;
    }
}

// ---------------------------------------------------------------------------
// fp16 HMMA GEMM — byte-identical to the round-10 best (160 threads:
// 4 consumer warps 64x64 + 1 producer warp), with __launch_bounds__(160, 2)
// pinning the 2-CTA/SM contract.
// 3-stage ring, stage 32KB (A @0, B @16384), barriers @0..47, stages @1024.
// mode 0: write Q/K fp16 [B,H,N,D] + V^T fp16 [B,H,D,N]; mode 1: fp32 out.
// ---------------------------------------------------------------------------
#define GEMM_SMEM (1024 + 3 * 32768)

__global__ __launch_bounds__(160, 2) void hgemm_kernel(
    const float* __restrict__ bias, float* __restrict__ out, int mode)
{
    extern __shared__ char smem[];
    const uint32_t sb = smem_u32(smem);
    const __half* A  = g_a16;
    const __half* Bt = (mode == 0) ? g_wq16 : g_wp16;

    const int tid  = threadIdx.x;
    const int lane = tid & 31, wid = tid >> 5;
    const int m0 = blockIdx.y * 128, n0 = blockIdx.x * 128;

    if (tid == 0) {
#pragma unroll
        for (int s = 0; s < 3; s++) {
            MBAR_INIT(sb + s * 16, 32);       // full: 32 producer threads
            MBAR_INIT(sb + s * 16 + 8, 128);  // empty: 128 consumer threads
        }
    }
    __syncthreads();   // the ONLY block-wide barrier

    if (wid == 4) {
        // ------------------------- producer warp -------------------------
        const char* aBase = (const char*)(A  + (size_t)m0 * E_);
        const char* bBase = (const char*)(Bt + (size_t)n0 * E_);
        for (int t = 0; t < KT_; t++) {
            const int s = t % 3;
            if (t >= 3) MBAR_WAIT(sb + s * 16 + 8, ((t - 3) / 3) & 1);
            const uint32_t sa = sb + 1024 + s * 32768;
            const char* aSrc = aBase + t * 128;
            const char* bSrc = bBase + t * 128;
#pragma unroll
            for (int i = 0; i < 32; i++) {
                const int u = i * 32 + lane;
                const int r = u >> 3, c = u & 7;
                cp_async16(sa + r * 128 + ((c ^ (r & 7)) << 4),
                           aSrc + (size_t)r * (E_ * 2) + c * 16);
            }
#pragma unroll
            for (int i = 0; i < 32; i++) {
                const int u = i * 32 + lane;
                const int r = u >> 3, c = u & 7;
                cp_async16(sa + 16384 + r * 128 + ((c ^ (r & 7)) << 4),
                           bSrc + (size_t)r * (E_ * 2) + c * 16);
            }
            MBAR_ARRIVE_CPASYNC(sb + s * 16);
        }
        return;
    }

    // --------------------------- consumer warps ---------------------------
    const int warp_m = wid & 1, warp_n = wid >> 1;

    float acc[4][8][4];
#pragma unroll
    for (int i = 0; i < 4; i++)
#pragma unroll
        for (int j = 0; j < 8; j++)
#pragma unroll
            for (int r = 0; r < 4; r++) acc[i][j][r] = 0.f;

    const int lane15 = lane & 15, lhalf = lane >> 4;
    const int ra  = warp_m * 64 + lane15;
    const int rbw = warp_n * 64 + lane15;

    for (int kt = 0; kt < KT_; kt++) {
        const int s = kt % 3;
        MBAR_WAIT(sb + s * 16, (kt / 3) & 1);   // full[s]

        const uint32_t sa  = sb + 1024 + s * 32768;
        const uint32_t sbB = sa + 16384;

        uint32_t afr[2][4][4], bfr[2][4][4];
        {
            const int kc = lhalf;
#pragma unroll
            for (int mi = 0; mi < 4; mi++) {
                const int r = ra + mi * 16;
                ldmatrix_x4(afr[0][mi], sa + r * 128 + ((kc ^ (r & 7)) << 4));
            }
#pragma unroll
            for (int ng = 0; ng < 4; ng++) {
                const int r = rbw + ng * 16;
                ldmatrix_x4(bfr[0][ng], sbB + r * 128 + ((kc ^ (r & 7)) << 4));
            }
        }
#pragma unroll
        for (int kk = 0; kk < 4; kk++) {
            const int cur = kk & 1, nxt = cur ^ 1;
            if (kk < 3) {
                const int kc = (kk + 1) * 2 + lhalf;
#pragma unroll
                for (int mi = 0; mi < 4; mi++) {
                    const int r = ra + mi * 16;
                    ldmatrix_x4(afr[nxt][mi], sa + r * 128 + ((kc ^ (r & 7)) << 4));
                }
#pragma unroll
                for (int ng = 0; ng < 4; ng++) {
                    const int r = rbw + ng * 16;
                    ldmatrix_x4(bfr[nxt][ng], sbB + r * 128 + ((kc ^ (r & 7)) << 4));
                }
            }
#pragma unroll
            for (int mi = 0; mi < 4; mi++)
#pragma unroll
                for (int nj = 0; nj < 8; nj++)
                    mma16816(acc[mi][nj], afr[cur][mi],
                             bfr[cur][nj >> 1][nj & 1],
                             bfr[cur][nj >> 1][(nj & 1) + 2]);
        }
        MBAR_ARRIVE(sb + s * 16 + 8);           // empty[s]
    }

    // Epilogue (consumers only)
    const int mrow = m0 + warp_m * 64 + (lane >> 2);
    const int ncb  = n0 + warp_n * 64 + (lane & 3) * 2;
#pragma unroll
    for (int mi = 0; mi < 4; mi++) {
#pragma unroll
        for (int nj = 0; nj < 8; nj++) {
            const int c  = ncb + nj * 8;
            const float b0 = bias[c], b1 = bias[c + 1];
            const int r0 = mrow + mi * 16;
            const float v00 = acc[mi][nj][0] + b0, v01 = acc[mi][nj][1] + b1;
            const float v10 = acc[mi][nj][2] + b0, v11 = acc[mi][nj][3] + b1;
            if (mode == 1) {
                float2 p0; p0.x = v00; p0.y = v01;
                float2 p1; p1.x = v10; p1.y = v11;
                *(float2*)&out[(size_t)r0 * E_ + c] = p0;
                *(float2*)&out[(size_t)(r0 + 8) * E_ + c] = p1;
                continue;
            }
            const int sec = c >> 10, e = c & 1023;
            const int hh = e >> 6, dd = e & 63;
            const int bb = r0 >> 10, nn = r0 & 1023;
            if (sec <= 1) {
                __half* dq = sec == 0 ? g_q16 : g_k16;
                const size_t i0 = (((size_t)bb * H_ + hh) * N_ + nn) * D_ + dd;
                *(uint32_t*)&dq[i0]          = packh2(v00, v01);
                *(uint32_t*)&dq[i0 + 8 * D_] = packh2(v10, v11);
            } else {
                const size_t i00 = (((size_t)bb * H_ + hh) * D_ + dd) * N_ + nn;
                g_vt16[i00]          = __float2half_rn(v00);
                g_vt16[i00 + N_]     = __float2half_rn(v01);
                g_vt16[i00 + 8]      = __float2half_rn(v10);
                g_vt16[i00 + N_ + 8] = __float2half_rn(v11);
            }
        }
    }
}

// ---------------------------------------------------------------------------
// Flash attention, fp16 HMMA — round-10 cooperative version (fastest
// measured): 128 q-rows per CTA (8 warps), 2-stage cp.async pipeline.
// ---------------------------------------------------------------------------
#define ATT_SMEM (2 * 16384)

__device__ __forceinline__ void att_load_tile(
    uint32_t st, int kv0, const __half* k16, const __half* vt16, int tid)
{
#pragma unroll
    for (int i = 0; i < 2; i++) {
        const int u = i * 256 + tid;
        const int r = u >> 3, c = u & 7;
        const uint32_t soff = r * 128 + ((c ^ (r & 7)) << 4);
        cp_async16(st + soff,        (const char*)k16  + (size_t)(kv0 + r) * 128 + c * 16);
        cp_async16(st + 8192 + soff, (const char*)vt16 + (size_t)r * 2048 + kv0 * 2 + c * 16);
    }
    cp_commit();
}

__global__ __launch_bounds__(256) void attn_kernel()
{
    extern __shared__ char smem[];
    const uint32_t sb = smem_u32(smem);

    const int tid = threadIdx.x;
    const int lane = tid & 31, w = tid >> 5;
    const int lane15 = lane & 15, lhalf = lane >> 4;
    const int q0 = blockIdx.x * 128;
    const int h  = blockIdx.y;
    const int b  = blockIdx.z;

    const size_t hb = (size_t)(b * H_ + h) * (N_ * D_);
    const __half* q16  = g_q16  + hb;
    const __half* k16  = g_k16  + hb;
    const __half* vt16 = g_vt16 + hb;

#pragma unroll
    for (int i = 0; i < 4; i++) {
        const int u = i * 256 + tid;
        const int r = u >> 3, c = u & 7;
        cp_async16(sb + r * 128 + ((c ^ (r & 7)) << 4),
                   (const char*)q16 + (size_t)(q0 + r) * 128 + c * 16);
    }
    cp_commit();
    asm volatile("cp.async.wait_group 0;" ::: "memory");
    __syncthreads();

    uint32_t qf[4][4];
    {
        const int r = w * 16 + lane15;
#pragma unroll
        for (int t = 0; t < 4; t++)
            ldmatrix_x4(qf[t], sb + r * 128 + (((t * 2 + lhalf) ^ (r & 7)) << 4));
    }
    __syncthreads();

    float mstate[2] = {-1e30f, -1e30f};
    float lstate[2] = {0.f, 0.f};
    float oacc[8][4];
#pragma unroll
    for (int j = 0; j < 8; j++)
#pragma unroll
        for (int r = 0; r < 4; r++) oacc[j][r] = 0.f;

    const float cexp = 0.18033688f;   // D^-0.5 * log2(e)

    att_load_tile(sb, 0, k16, vt16, tid);
    att_load_tile(sb + 16384, 64, k16, vt16, tid);

    for (int t = 0; t < 16; t++) {
        asm volatile("cp.async.wait_group 1;" ::: "memory");
        __syncthreads();
        const uint32_t stK = sb + (t & 1) * 16384;
        const uint32_t stV = stK + 8192;

        float sacc[8][4];
#pragma unroll
        for (int j = 0; j < 8; j++)
#pragma unroll
            for (int r = 0; r < 4; r++) sacc[j][r] = 0.f;

#pragma unroll
        for (int kvg = 0; kvg < 4; kvg++) {
            const int rb = kvg * 16 + lane15;
#pragma unroll
            for (int kk = 0; kk < 4; kk++) {
                uint32_t bf[4];
                ldmatrix_x4(bf, stK + rb * 128 + (((kk * 2 + lhalf) ^ (rb & 7)) << 4));
                mma16816(sacc[2 * kvg],     qf[kk], bf[0], bf[2]);
                mma16816(sacc[2 * kvg + 1], qf[kk], bf[1], bf[3]);
            }
        }

#pragma unroll
        for (int rr = 0; rr < 2; rr++) {
            float mx = -1e30f;
#pragma unroll
            for (int j = 0; j < 8; j++)
                mx = fmaxf(mx, fmaxf(sacc[j][rr * 2], sacc[j][rr * 2 + 1]));
            mx = fmaxf(mx, __shfl_xor_sync(0xffffffffu, mx, 1));
            mx = fmaxf(mx, __shfl_xor_sync(0xffffffffu, mx, 2));
            const float mnew  = fmaxf(mstate[rr], mx);
            const float alpha = exp2f((mstate[rr] - mnew) * cexp);
            mstate[rr] = mnew;
            float rs = 0.f;
#pragma unroll
            for (int j = 0; j < 8; j++) {
                const float p0 = exp2f((sacc[j][rr * 2]     - mnew) * cexp);
                const float p1 = exp2f((sacc[j][rr * 2 + 1] - mnew) * cexp);
                sacc[j][rr * 2] = p0; sacc[j][rr * 2 + 1] = p1;
                rs += p0 + p1;
            }
            rs += __shfl_xor_sync(0xffffffffu, rs, 1);
            rs += __shfl_xor_sync(0xffffffffu, rs, 2);
            lstate[rr] = lstate[rr] * alpha + rs;
#pragma unroll
            for (int j = 0; j < 8; j++) {
                oacc[j][rr * 2]     *= alpha;
                oacc[j][rr * 2 + 1] *= alpha;
            }
        }

        uint32_t pf[4][4];
#pragma unroll
        for (int kk = 0; kk < 4; kk++) {
#pragma unroll
            for (int q = 0; q < 4; q++) {
                const int tile = 2 * kk + (q >> 1);
                const int ri   = (q & 1) * 2;
                pf[kk][q] = packh2(sacc[tile][ri], sacc[tile][ri + 1]);
            }
        }

#pragma unroll
        for (int dg = 0; dg < 4; dg++) {
            const int rb = dg * 16 + lane15;
#pragma unroll
            for (int kk = 0; kk < 4; kk++) {
                uint32_t bf[4];
                ldmatrix_x4(bf, stV + rb * 128 + (((kk * 2 + lhalf) ^ (rb & 7)) << 4));
                mma16816(oacc[2 * dg],     pf[kk], bf[0], bf[2]);
                mma16816(oacc[2 * dg + 1], pf[kk], bf[1], bf[3]);
            }
        }

        __syncthreads();
        if (t + 2 < 16)
            att_load_tile(sb + (t & 1) * 16384, (t + 2) * 64, k16, vt16, tid);
        else
            cp_commit();
    }

    const float inv0 = 1.f / lstate[0];
    const float inv1 = 1.f / lstate[1];
    const int qrow = q0 + w * 16 + (lane >> 2);
    const size_t m0r = (size_t)(b * N_ + qrow) * E_;
    const size_t m1r = m0r + (size_t)8 * E_;
    const int colb = h * 64 + 2 * (lane & 3);
#pragma unroll
    for (int j = 0; j < 8; j++) {
        const int col = colb + 8 * j;
        *(uint32_t*)&g_a16[m0r + col] = packh2(oacc[j][0] * inv0, oacc[j][1] * inv0);
        *(uint32_t*)&g_a16[m1r + col] = packh2(oacc[j][2] * inv1, oacc[j][3] * inv1);
    }
}

// ---------------------------------------------------------------------------
extern "C" void kernel_launch(void* const* d_in, const int* in_sizes, int n_in,
                              void* d_out, int out_size)
{
    const float* x  = (const float*)d_in[0];
    const float* Wq = (const float*)d_in[1];
    const float* bq = (const float*)d_in[2];
    const float* Wp = (const float*)d_in[3];
    const float* bp = (const float*)d_in[4];
    float* out = (float*)d_out;

    cudaFuncSetAttribute(hgemm_kernel,
                         cudaFuncAttributeMaxDynamicSharedMemorySize, GEMM_SMEM);
    cudaFuncSetAttribute(attn_kernel,
                         cudaFuncAttributeMaxDynamicSharedMemorySize, ATT_SMEM);

    conv_all_kernel<<<M_ + 768 + 256, 256>>>(x, Wq, Wp);

    hgemm_kernel<<<dim3(QKV_N / 128, M_ / 128), 160, GEMM_SMEM>>>(bq, out, 0);

    attn_kernel<<<dim3(N_ / 128, H_, B_), 256, ATT_SMEM>>>();

    hgemm_kernel<<<dim3(E_ / 128, M_ / 128), 160, GEMM_SMEM>>>(bp, out, 1);
}

// round 14
// speedup vs baseline: 1.2761x; 1.0190x over previous
#include <cuda_runtime.h>
#include <cuda_fp16.h>
#include <cstdint>

#define B_   16
#define N_   1024
#define E_   1024
#define H_   16
#define D_   64
#define M_   (B_ * N_)        // 16384
#define QKV_N (3 * E_)        // 3072
#define KT_   (E_ / 64)       // 16 k-iters of 64

// ---------------------------------------------------------------------------
// Scratch (__device__ globals; no allocations)
// ---------------------------------------------------------------------------
static __device__ __align__(1024) __half g_q16 [(size_t)B_ * H_ * N_ * D_];
static __device__ __align__(1024) __half g_k16 [(size_t)B_ * H_ * N_ * D_];
static __device__ __align__(1024) __half g_vt16[(size_t)B_ * H_ * D_ * N_];  // V^T [B,H,D,N]
static __device__ __align__(1024) __half g_a16 [(size_t)M_ * E_];    // x, then attn out
static __device__ __align__(1024) __half g_wq16[(size_t)QKV_N * E_]; // Wqkv^T (n-major)
static __device__ __align__(1024) __half g_wp16[(size_t)E_ * E_];    // Wproj^T (n-major)

// ---------------------------------------------------------------------------
// helpers
// ---------------------------------------------------------------------------
__device__ __forceinline__ uint32_t smem_u32(const void* p) {
    uint32_t a;
    asm("{ .reg .u64 t; cvta.to.shared.u64 t, %1; cvt.u32.u64 %0, t; }"
        : "=r"(a) : "l"(p));
    return a;
}
__device__ __forceinline__ void cp_async16(uint32_t dst, const void* src) {
    asm volatile("cp.async.cg.shared.global [%0], [%1], 16;" :: "r"(dst), "l"(src));
}
__device__ __forceinline__ void cp_commit() {
    asm volatile("cp.async.commit_group;" ::: "memory");
}
__device__ __forceinline__ void ldmatrix_x4(uint32_t* d, uint32_t addr) {
    asm volatile("ldmatrix.sync.aligned.m8n8.x4.shared.b16 {%0,%1,%2,%3}, [%4];"
                 : "=r"(d[0]), "=r"(d[1]), "=r"(d[2]), "=r"(d[3]) : "r"(addr));
}
__device__ __forceinline__ void mma16816(float* c, const uint32_t* a,
                                         uint32_t b0, uint32_t b1) {
    asm volatile(
        "mma.sync.aligned.m16n8k16.row.col.f32.f16.f16.f32 "
        "{%0,%1,%2,%3}, {%4,%5,%6,%7}, {%8,%9}, {%0,%1,%2,%3};"
        : "+f"(c[0]), "+f"(c[1]), "+f"(c[2]), "+f"(c[3])
        : "r"(a[0]), "r"(a[1]), "r"(a[2]), "r"(a[3]), "r"(b0), "r"(b1));
}
__device__ __forceinline__ uint32_t packh2(float x, float y) {
    __half2 h = __floats2half2_rn(x, y);
    return *reinterpret_cast<uint32_t*>(&h);
}
#define MBAR_INIT(addr, cnt) \
    asm volatile("mbarrier.init.shared.b64 [%0], %1;" :: "r"(addr), "r"(cnt) : "memory")
#define MBAR_ARRIVE(addr) \
    asm volatile("mbarrier.arrive.shared.b64 _, [%0];" :: "r"(addr) : "memory")
#define MBAR_ARRIVE_CPASYNC(addr) \
    asm volatile("cp.async.mbarrier.arrive.noinc.shared.b64 [%0];" :: "r"(addr) : "memory")
#define MBAR_WAIT(addr, parity) do {                                          \
    asm volatile(                                                             \
        "{\n\t.reg .pred P1;\n\t"                                             \
        "WAIT_%=:\n\t"                                                        \
        "mbarrier.try_wait.parity.acquire.cta.shared::cta.b64 P1, [%0], %1, 0x989680;\n\t" \
        "@P1 bra.uni DONE_%=;\n\t"                                            \
        "bra.uni WAIT_%=;\n\t"                                                \
        "DONE_%=:\n\t}"                                                       \
        :: "r"(addr), "r"(parity) : "memory");                                \
} while (0)

// ---------------------------------------------------------------------------
// Fused conversion kernel (single launch):
//   blocks [0, 16384)         : x fp32 -> g_a16 fp16 (one row each)
//   blocks [16384, 16384+768) : Wq transpose tiles (16 kblk x 48 nblk)
//   blocks [+768, +768+256)   : Wp transpose tiles (16 kblk x 16 nblk)
// ---------------------------------------------------------------------------
__global__ __launch_bounds__(256) void conv_all_kernel(
    const float* __restrict__ x, const float* __restrict__ Wq,
    const float* __restrict__ Wp)
{
    __shared__ float tile[64][65];
    const int tid = threadIdx.x;
    const int bidx = blockIdx.x;

    if (bidx < M_) {
        const int k4 = tid << 2;
        float4 v = *(const float4*)(x + (size_t)bidx * E_ + k4);
        uint2 o;
        o.x = packh2(v.x, v.y);
        o.y = packh2(v.z, v.w);
        *(uint2*)&g_a16[(size_t)bidx * E_ + k4] = o;
        return;
    }

    const float* W;
    __half* dst;
    int Ncols, t;
    if (bidx < M_ + 768) {
        t = bidx - M_;       W = Wq; dst = g_wq16; Ncols = QKV_N;
    } else {
        t = bidx - M_ - 768; W = Wp; dst = g_wp16; Ncols = E_;
    }
    const int k0 = (t & 15) * 64;
    const int n0 = (t >> 4) * 64;

    const int lr = tid >> 6;
    const int lc = tid & 63;
#pragma unroll
    for (int i = 0; i < 16; i++) {
        const int r = lr + i * 4;
        tile[r][lc] = W[(size_t)(k0 + r) * Ncols + n0 + lc];
    }
    __syncthreads();

    const int nl = tid >> 2;
    const int kc = (tid & 3) << 4;
#pragma unroll
    for (int j = 0; j < 16; j += 4) {
        uint2 o;
        o.x = packh2(tile[kc + j][nl],     tile[kc + j + 1][nl]);
        o.y = packh2(tile[kc + j + 2][nl], tile[kc + j + 3][nl]);
        *(uint2*)&dst[(size_t)(n0 + nl) * E_ + k0 + kc + j] = o;
    }
}

// ---------------------------------------------------------------------------
// fp16 HMMA GEMM — round-13 best (160 threads: 4 consumer warps 64x64 +
// 1 producer warp), __launch_bounds__(160, 2) pins 2 CTA/SM.
// 3-stage ring, stage 32KB (A @0, B @16384), barriers @0..47, stages @1024.
// mode 0: write Q/K fp16 [B,H,N,D] + V^T fp16 [B,H,D,N]; mode 1: fp32 out.
// ---------------------------------------------------------------------------
#define GEMM_SMEM (1024 + 3 * 32768)

__global__ __launch_bounds__(160, 2) void hgemm_kernel(
    const float* __restrict__ bias, float* __restrict__ out, int mode)
{
    extern __shared__ char smem[];
    const uint32_t sb = smem_u32(smem);
    const __half* A  = g_a16;
    const __half* Bt = (mode == 0) ? g_wq16 : g_wp16;

    const int tid  = threadIdx.x;
    const int lane = tid & 31, wid = tid >> 5;
    const int m0 = blockIdx.y * 128, n0 = blockIdx.x * 128;

    if (tid == 0) {
#pragma unroll
        for (int s = 0; s < 3; s++) {
            MBAR_INIT(sb + s * 16, 32);       // full: 32 producer threads
            MBAR_INIT(sb + s * 16 + 8, 128);  // empty: 128 consumer threads
        }
    }
    __syncthreads();   // the ONLY block-wide barrier

    if (wid == 4) {
        // ------------------------- producer warp -------------------------
        const char* aBase = (const char*)(A  + (size_t)m0 * E_);
        const char* bBase = (const char*)(Bt + (size_t)n0 * E_);
        for (int t = 0; t < KT_; t++) {
            const int s = t % 3;
            if (t >= 3) MBAR_WAIT(sb + s * 16 + 8, ((t - 3) / 3) & 1);
            const uint32_t sa = sb + 1024 + s * 32768;
            const char* aSrc = aBase + t * 128;
            const char* bSrc = bBase + t * 128;
#pragma unroll
            for (int i = 0; i < 32; i++) {
                const int u = i * 32 + lane;
                const int r = u >> 3, c = u & 7;
                cp_async16(sa + r * 128 + ((c ^ (r & 7)) << 4),
                           aSrc + (size_t)r * (E_ * 2) + c * 16);
            }
#pragma unroll
            for (int i = 0; i < 32; i++) {
                const int u = i * 32 + lane;
                const int r = u >> 3, c = u & 7;
                cp_async16(sa + 16384 + r * 128 + ((c ^ (r & 7)) << 4),
                           bSrc + (size_t)r * (E_ * 2) + c * 16);
            }
            MBAR_ARRIVE_CPASYNC(sb + s * 16);
        }
        return;
    }

    // --------------------------- consumer warps ---------------------------
    const int warp_m = wid & 1, warp_n = wid >> 1;

    float acc[4][8][4];
#pragma unroll
    for (int i = 0; i < 4; i++)
#pragma unroll
        for (int j = 0; j < 8; j++)
#pragma unroll
            for (int r = 0; r < 4; r++) acc[i][j][r] = 0.f;

    const int lane15 = lane & 15, lhalf = lane >> 4;
    const int ra  = warp_m * 64 + lane15;
    const int rbw = warp_n * 64 + lane15;

    for (int kt = 0; kt < KT_; kt++) {
        const int s = kt % 3;
        MBAR_WAIT(sb + s * 16, (kt / 3) & 1);   // full[s]

        const uint32_t sa  = sb + 1024 + s * 32768;
        const uint32_t sbB = sa + 16384;

        uint32_t afr[2][4][4], bfr[2][4][4];
        {
            const int kc = lhalf;
#pragma unroll
            for (int mi = 0; mi < 4; mi++) {
                const int r = ra + mi * 16;
                ldmatrix_x4(afr[0][mi], sa + r * 128 + ((kc ^ (r & 7)) << 4));
            }
#pragma unroll
            for (int ng = 0; ng < 4; ng++) {
                const int r = rbw + ng * 16;
                ldmatrix_x4(bfr[0][ng], sbB + r * 128 + ((kc ^ (r & 7)) << 4));
            }
        }
#pragma unroll
        for (int kk = 0; kk < 4; kk++) {
            const int cur = kk & 1, nxt = cur ^ 1;
            if (kk < 3) {
                const int kc = (kk + 1) * 2 + lhalf;
#pragma unroll
                for (int mi = 0; mi < 4; mi++) {
                    const int r = ra + mi * 16;
                    ldmatrix_x4(afr[nxt][mi], sa + r * 128 + ((kc ^ (r & 7)) << 4));
                }
#pragma unroll
                for (int ng = 0; ng < 4; ng++) {
                    const int r = rbw + ng * 16;
                    ldmatrix_x4(bfr[nxt][ng], sbB + r * 128 + ((kc ^ (r & 7)) << 4));
                }
            }
#pragma unroll
            for (int mi = 0; mi < 4; mi++)
#pragma unroll
                for (int nj = 0; nj < 8; nj++)
                    mma16816(acc[mi][nj], afr[cur][mi],
                             bfr[cur][nj >> 1][nj & 1],
                             bfr[cur][nj >> 1][(nj & 1) + 2]);
        }
        MBAR_ARRIVE(sb + s * 16 + 8);           // empty[s]
    }

    // Epilogue (consumers only)
    const int mrow = m0 + warp_m * 64 + (lane >> 2);
    const int ncb  = n0 + warp_n * 64 + (lane & 3) * 2;
#pragma unroll
    for (int mi = 0; mi < 4; mi++) {
#pragma unroll
        for (int nj = 0; nj < 8; nj++) {
            const int c  = ncb + nj * 8;
            const float b0 = bias[c], b1 = bias[c + 1];
            const int r0 = mrow + mi * 16;
            const float v00 = acc[mi][nj][0] + b0, v01 = acc[mi][nj][1] + b1;
            const float v10 = acc[mi][nj][2] + b0, v11 = acc[mi][nj][3] + b1;
            if (mode == 1) {
                float2 p0; p0.x = v00; p0.y = v01;
                float2 p1; p1.x = v10; p1.y = v11;
                *(float2*)&out[(size_t)r0 * E_ + c] = p0;
                *(float2*)&out[(size_t)(r0 + 8) * E_ + c] = p1;
                continue;
            }
            const int sec = c >> 10, e = c & 1023;
            const int hh = e >> 6, dd = e & 63;
            const int bb = r0 >> 10, nn = r0 & 1023;
            if (sec <= 1) {
                __half* dq = sec == 0 ? g_q16 : g_k16;
                const size_t i0 = (((size_t)bb * H_ + hh) * N_ + nn) * D_ + dd;
                *(uint32_t*)&dq[i0]          = packh2(v00, v01);
                *(uint32_t*)&dq[i0 + 8 * D_] = packh2(v10, v11);
            } else {
                const size_t i00 = (((size_t)bb * H_ + hh) * D_ + dd) * N_ + nn;
                g_vt16[i00]          = __float2half_rn(v00);
                g_vt16[i00 + N_]     = __float2half_rn(v01);
                g_vt16[i00 + 8]      = __float2half_rn(v10);
                g_vt16[i00 + N_ + 8] = __float2half_rn(v11);
            }
        }
    }
}

// ---------------------------------------------------------------------------
// Flash attention, fp16 HMMA — 64 q-rows per CTA, 128 threads (4 warps),
// 2-stage cp.async pipeline, __launch_bounds__(128, 2) -> 2 CTA/SM so the
// co-resident CTA's MMAs cover this CTA's softmax phases.
// stage: K @0 (8KB), V^T @8192 (8KB); stride 16384; total 32KB.
// ---------------------------------------------------------------------------
#define ATT_SMEM (2 * 16384)

__device__ __forceinline__ void att_load_tile(
    uint32_t st, int kv0, const __half* k16, const __half* vt16, int tid)
{
#pragma unroll
    for (int i = 0; i < 4; i++) {
        const int u = i * 128 + tid;
        const int r = u >> 3, c = u & 7;
        const uint32_t soff = r * 128 + ((c ^ (r & 7)) << 4);
        cp_async16(st + soff,        (const char*)k16  + (size_t)(kv0 + r) * 128 + c * 16);
        cp_async16(st + 8192 + soff, (const char*)vt16 + (size_t)r * 2048 + kv0 * 2 + c * 16);
    }
    cp_commit();
}

__global__ __launch_bounds__(128, 2) void attn_kernel()
{
    extern __shared__ char smem[];
    const uint32_t sb = smem_u32(smem);

    const int tid = threadIdx.x;
    const int lane = tid & 31, w = tid >> 5;
    const int lane15 = lane & 15, lhalf = lane >> 4;
    const int q0 = blockIdx.x * 64;
    const int h  = blockIdx.y;
    const int b  = blockIdx.z;

    const size_t hb = (size_t)(b * H_ + h) * (N_ * D_);
    const __half* q16  = g_q16  + hb;
    const __half* k16  = g_k16  + hb;
    const __half* vt16 = g_vt16 + hb;

    // stage Q in stage-0 K region, extract fragments
#pragma unroll
    for (int i = 0; i < 4; i++) {
        const int u = i * 128 + tid;
        const int r = u >> 3, c = u & 7;
        cp_async16(sb + r * 128 + ((c ^ (r & 7)) << 4),
                   (const char*)q16 + (size_t)(q0 + r) * 128 + c * 16);
    }
    cp_commit();
    asm volatile("cp.async.wait_group 0;" ::: "memory");
    __syncthreads();

    uint32_t qf[4][4];
    {
        const int r = w * 16 + lane15;
#pragma unroll
        for (int t = 0; t < 4; t++)
            ldmatrix_x4(qf[t], sb + r * 128 + (((t * 2 + lhalf) ^ (r & 7)) << 4));
    }
    __syncthreads();

    float mstate[2] = {-1e30f, -1e30f};
    float lstate[2] = {0.f, 0.f};
    float oacc[8][4];
#pragma unroll
    for (int j = 0; j < 8; j++)
#pragma unroll
        for (int r = 0; r < 4; r++) oacc[j][r] = 0.f;

    const float cexp = 0.18033688f;   // D^-0.5 * log2(e)

    att_load_tile(sb, 0, k16, vt16, tid);
    att_load_tile(sb + 16384, 64, k16, vt16, tid);

    for (int t = 0; t < 16; t++) {
        asm volatile("cp.async.wait_group 1;" ::: "memory");
        __syncthreads();
        const uint32_t stK = sb + (t & 1) * 16384;
        const uint32_t stV = stK + 8192;

        float sacc[8][4];
#pragma unroll
        for (int j = 0; j < 8; j++)
#pragma unroll
            for (int r = 0; r < 4; r++) sacc[j][r] = 0.f;

#pragma unroll
        for (int kvg = 0; kvg < 4; kvg++) {
            const int rb = kvg * 16 + lane15;
#pragma unroll
            for (int kk = 0; kk < 4; kk++) {
                uint32_t bf[4];
                ldmatrix_x4(bf, stK + rb * 128 + (((kk * 2 + lhalf) ^ (rb & 7)) << 4));
                mma16816(sacc[2 * kvg],     qf[kk], bf[0], bf[2]);
                mma16816(sacc[2 * kvg + 1], qf[kk], bf[1], bf[3]);
            }
        }

#pragma unroll
        for (int rr = 0; rr < 2; rr++) {
            float mx = -1e30f;
#pragma unroll
            for (int j = 0; j < 8; j++)
                mx = fmaxf(mx, fmaxf(sacc[j][rr * 2], sacc[j][rr * 2 + 1]));
            mx = fmaxf(mx, __shfl_xor_sync(0xffffffffu, mx, 1));
            mx = fmaxf(mx, __shfl_xor_sync(0xffffffffu, mx, 2));
            const float mnew  = fmaxf(mstate[rr], mx);
            const float alpha = exp2f((mstate[rr] - mnew) * cexp);
            mstate[rr] = mnew;
            float rs = 0.f;
#pragma unroll
            for (int j = 0; j < 8; j++) {
                const float p0 = exp2f((sacc[j][rr * 2]     - mnew) * cexp);
                const float p1 = exp2f((sacc[j][rr * 2 + 1] - mnew) * cexp);
                sacc[j][rr * 2] = p0; sacc[j][rr * 2 + 1] = p1;
                rs += p0 + p1;
            }
            rs += __shfl_xor_sync(0xffffffffu, rs, 1);
            rs += __shfl_xor_sync(0xffffffffu, rs, 2);
            lstate[rr] = lstate[rr] * alpha + rs;
#pragma unroll
            for (int j = 0; j < 8; j++) {
                oacc[j][rr * 2]     *= alpha;
                oacc[j][rr * 2 + 1] *= alpha;
            }
        }

        // P fragments in registers (C-frag layout == A-frag layout)
        uint32_t pf[4][4];
#pragma unroll
        for (int kk = 0; kk < 4; kk++) {
#pragma unroll
            for (int q = 0; q < 4; q++) {
                const int tile = 2 * kk + (q >> 1);
                const int ri   = (q & 1) * 2;
                pf[kk][q] = packh2(sacc[tile][ri], sacc[tile][ri + 1]);
            }
        }

#pragma unroll
        for (int dg = 0; dg < 4; dg++) {
            const int rb = dg * 16 + lane15;
#pragma unroll
            for (int kk = 0; kk < 4; kk++) {
                uint32_t bf[4];
                ldmatrix_x4(bf, stV + rb * 128 + (((kk * 2 + lhalf) ^ (rb & 7)) << 4));
                mma16816(oacc[2 * dg],     pf[kk], bf[0], bf[2]);
                mma16816(oacc[2 * dg + 1], pf[kk], bf[1], bf[3]);
            }
        }

        __syncthreads();
        if (t + 2 < 16)
            att_load_tile(sb + (t & 1) * 16384, (t + 2) * 64, k16, vt16, tid);
        else
            cp_commit();
    }

    // epilogue: normalize, write fp16 O rows into g_a16 [M, E]
    const float inv0 = 1.f / lstate[0];
    const float inv1 = 1.f / lstate[1];
    const int qrow = q0 + w * 16 + (lane >> 2);
    const size_t m0r = (size_t)(b * N_ + qrow) * E_;
    const size_t m1r = m0r + (size_t)8 * E_;
    const int colb = h * 64 + 2 * (lane & 3);
#pragma unroll
    for (int j = 0; j < 8; j++) {
        const int col = colb + 8 * j;
        *(uint32_t*)&g_a16[m0r + col] = packh2(oacc[j][0] * inv0, oacc[j][1] * inv0);
        *(uint32_t*)&g_a16[m1r + col] = packh2(oacc[j][2] * inv1, oacc[j][3] * inv1);
    }
}

// ---------------------------------------------------------------------------
extern "C" void kernel_launch(void* const* d_in, const int* in_sizes, int n_in,
                              void* d_out, int out_size)
{
    const float* x  = (const float*)d_in[0];
    const float* Wq = (const float*)d_in[1];
    const float* bq = (const float*)d_in[2];
    const float* Wp = (const float*)d_in[3];
    const float* bp = (const float*)d_in[4];
    float* out = (float*)d_out;

    cudaFuncSetAttribute(hgemm_kernel,
                         cudaFuncAttributeMaxDynamicSharedMemorySize, GEMM_SMEM);
    cudaFuncSetAttribute(attn_kernel,
                         cudaFuncAttributeMaxDynamicSharedMemorySize, ATT_SMEM);

    conv_all_kernel<<<M_ + 768 + 256, 256>>>(x, Wq, Wp);

    hgemm_kernel<<<dim3(QKV_N / 128, M_ / 128), 160, GEMM_SMEM>>>(bq, out, 0);

    attn_kernel<<<dim3(N_ / 64, H_, B_), 128, ATT_SMEM>>>();

    hgemm_kernel<<<dim3(E_ / 128, M_ / 128), 160, GEMM_SMEM>>>(bp, out, 1);
}

// round 15
// speedup vs baseline: 1.2765x; 1.0003x over previous
#include <cuda_runtime.h>
#include <cuda_fp16.h>
#include <cstdint>

#define B_   16
#define N_   1024
#define E_   1024
#define H_   16
#define D_   64
#define M_   (B_ * N_)        // 16384
#define QKV_N (3 * E_)        // 3072
#define KT_   (E_ / 64)       // 16 k-iters of 64

// ---------------------------------------------------------------------------
// Scratch (__device__ globals; no allocations)
// ---------------------------------------------------------------------------
static __device__ __align__(1024) __half g_q16 [(size_t)B_ * H_ * N_ * D_];
static __device__ __align__(1024) __half g_k16 [(size_t)B_ * H_ * N_ * D_];
static __device__ __align__(1024) __half g_vt16[(size_t)B_ * H_ * D_ * N_];  // V^T [B,H,D,N]
static __device__ __align__(1024) __half g_a16 [(size_t)M_ * E_];    // x, then attn out
static __device__ __align__(1024) __half g_wq16[(size_t)QKV_N * E_]; // Wqkv^T (n-major)
static __device__ __align__(1024) __half g_wp16[(size_t)E_ * E_];    // Wproj^T (n-major)

// ---------------------------------------------------------------------------
// helpers
// ---------------------------------------------------------------------------
__device__ __forceinline__ uint32_t smem_u32(const void* p) {
    uint32_t a;
    asm("{ .reg .u64 t; cvta.to.shared.u64 t, %1; cvt.u32.u64 %0, t; }"
        : "=r"(a) : "l"(p));
    return a;
}
__device__ __forceinline__ void cp_async16(uint32_t dst, const void* src) {
    asm volatile("cp.async.cg.shared.global [%0], [%1], 16;" :: "r"(dst), "l"(src));
}
__device__ __forceinline__ void cp_commit() {
    asm volatile("cp.async.commit_group;" ::: "memory");
}
__device__ __forceinline__ void ldmatrix_x4(uint32_t* d, uint32_t addr) {
    asm volatile("ldmatrix.sync.aligned.m8n8.x4.shared.b16 {%0,%1,%2,%3}, [%4];"
                 : "=r"(d[0]), "=r"(d[1]), "=r"(d[2]), "=r"(d[3]) : "r"(addr));
}
__device__ __forceinline__ void mma16816(float* c, const uint32_t* a,
                                         uint32_t b0, uint32_t b1) {
    asm volatile(
        "mma.sync.aligned.m16n8k16.row.col.f32.f16.f16.f32 "
        "{%0,%1,%2,%3}, {%4,%5,%6,%7}, {%8,%9}, {%0,%1,%2,%3};"
        : "+f"(c[0]), "+f"(c[1]), "+f"(c[2]), "+f"(c[3])
        : "r"(a[0]), "r"(a[1]), "r"(a[2]), "r"(a[3]), "r"(b0), "r"(b1));
}
__device__ __forceinline__ uint32_t packh2(float x, float y) {
    __half2 h = __floats2half2_rn(x, y);
    return *reinterpret_cast<uint32_t*>(&h);
}
__device__ __forceinline__ float ex2(float x) {
    float y;
    asm("ex2.approx.f32 %0, %1;" : "=f"(y) : "f"(x));
    return y;
}
#define MBAR_INIT(addr, cnt) \
    asm volatile("mbarrier.init.shared.b64 [%0], %1;" :: "r"(addr), "r"(cnt) : "memory")
#define MBAR_ARRIVE(addr) \
    asm volatile("mbarrier.arrive.shared.b64 _, [%0];" :: "r"(addr) : "memory")
#define MBAR_ARRIVE_CPASYNC(addr) \
    asm volatile("cp.async.mbarrier.arrive.noinc.shared.b64 [%0];" :: "r"(addr) : "memory")
#define MBAR_WAIT(addr, parity) do {                                          \
    asm volatile(                                                             \
        "{\n\t.reg .pred P1;\n\t"                                             \
        "WAIT_%=:\n\t"                                                        \
        "mbarrier.try_wait.parity.acquire.cta.shared::cta.b64 P1, [%0], %1, 0x989680;\n\t" \
        "@P1 bra.uni DONE_%=;\n\t"                                            \
        "bra.uni WAIT_%=;\n\t"                                                \
        "DONE_%=:\n\t}"                                                       \
        :: "r"(addr), "r"(parity) : "memory");                                \
} while (0)

// ---------------------------------------------------------------------------
// Fused conversion kernel (single launch):
//   blocks [0, 16384)         : x fp32 -> g_a16 fp16 (one row each)
//   blocks [16384, 16384+768) : Wq transpose tiles (16 kblk x 48 nblk)
//   blocks [+768, +768+256)   : Wp transpose tiles (16 kblk x 16 nblk)
// ---------------------------------------------------------------------------
__global__ __launch_bounds__(256) void conv_all_kernel(
    const float* __restrict__ x, const float* __restrict__ Wq,
    const float* __restrict__ Wp)
{
    __shared__ float tile[64][65];
    const int tid = threadIdx.x;
    const int bidx = blockIdx.x;

    if (bidx < M_) {
        const int k4 = tid << 2;
        float4 v = *(const float4*)(x + (size_t)bidx * E_ + k4);
        uint2 o;
        o.x = packh2(v.x, v.y);
        o.y = packh2(v.z, v.w);
        *(uint2*)&g_a16[(size_t)bidx * E_ + k4] = o;
        return;
    }

    const float* W;
    __half* dst;
    int Ncols, t;
    if (bidx < M_ + 768) {
        t = bidx - M_;       W = Wq; dst = g_wq16; Ncols = QKV_N;
    } else {
        t = bidx - M_ - 768; W = Wp; dst = g_wp16; Ncols = E_;
    }
    const int k0 = (t & 15) * 64;
    const int n0 = (t >> 4) * 64;

    const int lr = tid >> 6;
    const int lc = tid & 63;
#pragma unroll
    for (int i = 0; i < 16; i++) {
        const int r = lr + i * 4;
        tile[r][lc] = W[(size_t)(k0 + r) * Ncols + n0 + lc];
    }
    __syncthreads();

    const int nl = tid >> 2;
    const int kc = (tid & 3) << 4;
#pragma unroll
    for (int j = 0; j < 16; j += 4) {
        uint2 o;
        o.x = packh2(tile[kc + j][nl],     tile[kc + j + 1][nl]);
        o.y = packh2(tile[kc + j + 2][nl], tile[kc + j + 3][nl]);
        *(uint2*)&dst[(size_t)(n0 + nl) * E_ + k0 + kc + j] = o;
    }
}

// ---------------------------------------------------------------------------
// fp16 HMMA GEMM — round-13 best (160 threads: 4 consumer warps 64x64 +
// 1 producer warp), __launch_bounds__(160, 2) pins 2 CTA/SM.
// 3-stage ring, stage 32KB (A @0, B @16384), barriers @0..47, stages @1024.
// mode 0: write Q/K fp16 [B,H,N,D] + V^T fp16 [B,H,D,N]; mode 1: fp32 out.
// ---------------------------------------------------------------------------
#define GEMM_SMEM (1024 + 3 * 32768)

__global__ __launch_bounds__(160, 2) void hgemm_kernel(
    const float* __restrict__ bias, float* __restrict__ out, int mode)
{
    extern __shared__ char smem[];
    const uint32_t sb = smem_u32(smem);
    const __half* A  = g_a16;
    const __half* Bt = (mode == 0) ? g_wq16 : g_wp16;

    const int tid  = threadIdx.x;
    const int lane = tid & 31, wid = tid >> 5;
    const int m0 = blockIdx.y * 128, n0 = blockIdx.x * 128;

    if (tid == 0) {
#pragma unroll
        for (int s = 0; s < 3; s++) {
            MBAR_INIT(sb + s * 16, 32);       // full: 32 producer threads
            MBAR_INIT(sb + s * 16 + 8, 128);  // empty: 128 consumer threads
        }
    }
    __syncthreads();   // the ONLY block-wide barrier

    if (wid == 4) {
        // ------------------------- producer warp -------------------------
        const char* aBase = (const char*)(A  + (size_t)m0 * E_);
        const char* bBase = (const char*)(Bt + (size_t)n0 * E_);
        for (int t = 0; t < KT_; t++) {
            const int s = t % 3;
            if (t >= 3) MBAR_WAIT(sb + s * 16 + 8, ((t - 3) / 3) & 1);
            const uint32_t sa = sb + 1024 + s * 32768;
            const char* aSrc = aBase + t * 128;
            const char* bSrc = bBase + t * 128;
#pragma unroll
            for (int i = 0; i < 32; i++) {
                const int u = i * 32 + lane;
                const int r = u >> 3, c = u & 7;
                cp_async16(sa + r * 128 + ((c ^ (r & 7)) << 4),
                           aSrc + (size_t)r * (E_ * 2) + c * 16);
            }
#pragma unroll
            for (int i = 0; i < 32; i++) {
                const int u = i * 32 + lane;
                const int r = u >> 3, c = u & 7;
                cp_async16(sa + 16384 + r * 128 + ((c ^ (r & 7)) << 4),
                           bSrc + (size_t)r * (E_ * 2) + c * 16);
            }
            MBAR_ARRIVE_CPASYNC(sb + s * 16);
        }
        return;
    }

    // --------------------------- consumer warps ---------------------------
    const int warp_m = wid & 1, warp_n = wid >> 1;

    float acc[4][8][4];
#pragma unroll
    for (int i = 0; i < 4; i++)
#pragma unroll
        for (int j = 0; j < 8; j++)
#pragma unroll
            for (int r = 0; r < 4; r++) acc[i][j][r] = 0.f;

    const int lane15 = lane & 15, lhalf = lane >> 4;
    const int ra  = warp_m * 64 + lane15;
    const int rbw = warp_n * 64 + lane15;

    for (int kt = 0; kt < KT_; kt++) {
        const int s = kt % 3;
        MBAR_WAIT(sb + s * 16, (kt / 3) & 1);   // full[s]

        const uint32_t sa  = sb + 1024 + s * 32768;
        const uint32_t sbB = sa + 16384;

        uint32_t afr[2][4][4], bfr[2][4][4];
        {
            const int kc = lhalf;
#pragma unroll
            for (int mi = 0; mi < 4; mi++) {
                const int r = ra + mi * 16;
                ldmatrix_x4(afr[0][mi], sa + r * 128 + ((kc ^ (r & 7)) << 4));
            }
#pragma unroll
            for (int ng = 0; ng < 4; ng++) {
                const int r = rbw + ng * 16;
                ldmatrix_x4(bfr[0][ng], sbB + r * 128 + ((kc ^ (r & 7)) << 4));
            }
        }
#pragma unroll
        for (int kk = 0; kk < 4; kk++) {
            const int cur = kk & 1, nxt = cur ^ 1;
            if (kk < 3) {
                const int kc = (kk + 1) * 2 + lhalf;
#pragma unroll
                for (int mi = 0; mi < 4; mi++) {
                    const int r = ra + mi * 16;
                    ldmatrix_x4(afr[nxt][mi], sa + r * 128 + ((kc ^ (r & 7)) << 4));
                }
#pragma unroll
                for (int ng = 0; ng < 4; ng++) {
                    const int r = rbw + ng * 16;
                    ldmatrix_x4(bfr[nxt][ng], sbB + r * 128 + ((kc ^ (r & 7)) << 4));
                }
            }
#pragma unroll
            for (int mi = 0; mi < 4; mi++)
#pragma unroll
                for (int nj = 0; nj < 8; nj++)
                    mma16816(acc[mi][nj], afr[cur][mi],
                             bfr[cur][nj >> 1][nj & 1],
                             bfr[cur][nj >> 1][(nj & 1) + 2]);
        }
        MBAR_ARRIVE(sb + s * 16 + 8);           // empty[s]
    }

    // Epilogue (consumers only)
    const int mrow = m0 + warp_m * 64 + (lane >> 2);
    const int ncb  = n0 + warp_n * 64 + (lane & 3) * 2;
#pragma unroll
    for (int mi = 0; mi < 4; mi++) {
#pragma unroll
        for (int nj = 0; nj < 8; nj++) {
            const int c  = ncb + nj * 8;
            const float b0 = bias[c], b1 = bias[c + 1];
            const int r0 = mrow + mi * 16;
            const float v00 = acc[mi][nj][0] + b0, v01 = acc[mi][nj][1] + b1;
            const float v10 = acc[mi][nj][2] + b0, v11 = acc[mi][nj][3] + b1;
            if (mode == 1) {
                float2 p0; p0.x = v00; p0.y = v01;
                float2 p1; p1.x = v10; p1.y = v11;
                *(float2*)&out[(size_t)r0 * E_ + c] = p0;
                *(float2*)&out[(size_t)(r0 + 8) * E_ + c] = p1;
                continue;
            }
            const int sec = c >> 10, e = c & 1023;
            const int hh = e >> 6, dd = e & 63;
            const int bb = r0 >> 10, nn = r0 & 1023;
            if (sec <= 1) {
                __half* dq = sec == 0 ? g_q16 : g_k16;
                const size_t i0 = (((size_t)bb * H_ + hh) * N_ + nn) * D_ + dd;
                *(uint32_t*)&dq[i0]          = packh2(v00, v01);
                *(uint32_t*)&dq[i0 + 8 * D_] = packh2(v10, v11);
            } else {
                const size_t i00 = (((size_t)bb * H_ + hh) * D_ + dd) * N_ + nn;
                g_vt16[i00]          = __float2half_rn(v00);
                g_vt16[i00 + N_]     = __float2half_rn(v01);
                g_vt16[i00 + 8]      = __float2half_rn(v10);
                g_vt16[i00 + N_ + 8] = __float2half_rn(v11);
            }
        }
    }
}

// ---------------------------------------------------------------------------
// Flash attention, fp16 HMMA — 64 q-rows per CTA, 128 threads (4 warps),
// __launch_bounds__(128, 2) -> 2 CTA/SM. THREE-stage K/V ring with ONE
// __syncthreads per kv-iter (wait -> sync -> issue t+2 -> compute).
// Stage = 16KB (K @0, V^T @8192); stages at sb + s*16384; Q staged in
// stage 0 before the prologue. ex2.approx for the exponentials.
// ---------------------------------------------------------------------------
#define ATT_SMEM (3 * 16384)

__device__ __forceinline__ void att_load_tile(
    uint32_t st, int kv0, const __half* k16, const __half* vt16, int tid)
{
#pragma unroll
    for (int i = 0; i < 4; i++) {
        const int u = i * 128 + tid;
        const int r = u >> 3, c = u & 7;
        const uint32_t soff = r * 128 + ((c ^ (r & 7)) << 4);
        cp_async16(st + soff,        (const char*)k16  + (size_t)(kv0 + r) * 128 + c * 16);
        cp_async16(st + 8192 + soff, (const char*)vt16 + (size_t)r * 2048 + kv0 * 2 + c * 16);
    }
    cp_commit();
}

__global__ __launch_bounds__(128, 2) void attn_kernel()
{
    extern __shared__ char smem[];
    const uint32_t sb = smem_u32(smem);

    const int tid = threadIdx.x;
    const int lane = tid & 31, w = tid >> 5;
    const int lane15 = lane & 15, lhalf = lane >> 4;
    const int q0 = blockIdx.x * 64;
    const int h  = blockIdx.y;
    const int b  = blockIdx.z;

    const size_t hb = (size_t)(b * H_ + h) * (N_ * D_);
    const __half* q16  = g_q16  + hb;
    const __half* k16  = g_k16  + hb;
    const __half* vt16 = g_vt16 + hb;

    // stage Q in stage-0 region, extract fragments
#pragma unroll
    for (int i = 0; i < 4; i++) {
        const int u = i * 128 + tid;
        const int r = u >> 3, c = u & 7;
        cp_async16(sb + r * 128 + ((c ^ (r & 7)) << 4),
                   (const char*)q16 + (size_t)(q0 + r) * 128 + c * 16);
    }
    cp_commit();
    asm volatile("cp.async.wait_group 0;" ::: "memory");
    __syncthreads();

    uint32_t qf[4][4];
    {
        const int r = w * 16 + lane15;
#pragma unroll
        for (int t = 0; t < 4; t++)
            ldmatrix_x4(qf[t], sb + r * 128 + (((t * 2 + lhalf) ^ (r & 7)) << 4));
    }
    __syncthreads();

    float mstate[2] = {-1e30f, -1e30f};
    float lstate[2] = {0.f, 0.f};
    float oacc[8][4];
#pragma unroll
    for (int j = 0; j < 8; j++)
#pragma unroll
        for (int r = 0; r < 4; r++) oacc[j][r] = 0.f;

    const float cexp = 0.18033688f;   // D^-0.5 * log2(e)

    att_load_tile(sb, 0, k16, vt16, tid);
    att_load_tile(sb + 16384, 64, k16, vt16, tid);

    for (int t = 0; t < 16; t++) {
        asm volatile("cp.async.wait_group 1;" ::: "memory");
        __syncthreads();   // data-ready for t AND safe reuse of stage (t+2)%3
        if (t + 2 < 16)
            att_load_tile(sb + ((t + 2) % 3) * 16384, (t + 2) * 64, k16, vt16, tid);
        else
            cp_commit();   // keep group counting uniform

        const uint32_t stK = sb + (t % 3) * 16384;
        const uint32_t stV = stK + 8192;

        float sacc[8][4];
#pragma unroll
        for (int j = 0; j < 8; j++)
#pragma unroll
            for (int r = 0; r < 4; r++) sacc[j][r] = 0.f;

#pragma unroll
        for (int kvg = 0; kvg < 4; kvg++) {
            const int rb = kvg * 16 + lane15;
#pragma unroll
            for (int kk = 0; kk < 4; kk++) {
                uint32_t bf[4];
                ldmatrix_x4(bf, stK + rb * 128 + (((kk * 2 + lhalf) ^ (rb & 7)) << 4));
                mma16816(sacc[2 * kvg],     qf[kk], bf[0], bf[2]);
                mma16816(sacc[2 * kvg + 1], qf[kk], bf[1], bf[3]);
            }
        }

#pragma unroll
        for (int rr = 0; rr < 2; rr++) {
            float mx = -1e30f;
#pragma unroll
            for (int j = 0; j < 8; j++)
                mx = fmaxf(mx, fmaxf(sacc[j][rr * 2], sacc[j][rr * 2 + 1]));
            mx = fmaxf(mx, __shfl_xor_sync(0xffffffffu, mx, 1));
            mx = fmaxf(mx, __shfl_xor_sync(0xffffffffu, mx, 2));
            const float mnew  = fmaxf(mstate[rr], mx);
            const float alpha = ex2((mstate[rr] - mnew) * cexp);
            mstate[rr] = mnew;
            float rs = 0.f;
#pragma unroll
            for (int j = 0; j < 8; j++) {
                const float p0 = ex2((sacc[j][rr * 2]     - mnew) * cexp);
                const float p1 = ex2((sacc[j][rr * 2 + 1] - mnew) * cexp);
                sacc[j][rr * 2] = p0; sacc[j][rr * 2 + 1] = p1;
                rs += p0 + p1;
            }
            rs += __shfl_xor_sync(0xffffffffu, rs, 1);
            rs += __shfl_xor_sync(0xffffffffu, rs, 2);
            lstate[rr] = lstate[rr] * alpha + rs;
#pragma unroll
            for (int j = 0; j < 8; j++) {
                oacc[j][rr * 2]     *= alpha;
                oacc[j][rr * 2 + 1] *= alpha;
            }
        }

        // P fragments in registers (C-frag layout == A-frag layout)
        uint32_t pf[4][4];
#pragma unroll
        for (int kk = 0; kk < 4; kk++) {
#pragma unroll
            for (int q = 0; q < 4; q++) {
                const int tile = 2 * kk + (q >> 1);
                const int ri   = (q & 1) * 2;
                pf[kk][q] = packh2(sacc[tile][ri], sacc[tile][ri + 1]);
            }
        }

#pragma unroll
        for (int dg = 0; dg < 4; dg++) {
            const int rb = dg * 16 + lane15;
#pragma unroll
            for (int kk = 0; kk < 4; kk++) {
                uint32_t bf[4];
                ldmatrix_x4(bf, stV + rb * 128 + (((kk * 2 + lhalf) ^ (rb & 7)) << 4));
                mma16816(oacc[2 * dg],     pf[kk], bf[0], bf[2]);
                mma16816(oacc[2 * dg + 1], pf[kk], bf[1], bf[3]);
            }
        }
    }

    // epilogue: normalize, write fp16 O rows into g_a16 [M, E]
    const float inv0 = 1.f / lstate[0];
    const float inv1 = 1.f / lstate[1];
    const int qrow = q0 + w * 16 + (lane >> 2);
    const size_t m0r = (size_t)(b * N_ + qrow) * E_;
    const size_t m1r = m0r + (size_t)8 * E_;
    const int colb = h * 64 + 2 * (lane & 3);
#pragma unroll
    for (int j = 0; j < 8; j++) {
        const int col = colb + 8 * j;
        *(uint32_t*)&g_a16[m0r + col] = packh2(oacc[j][0] * inv0, oacc[j][1] * inv0);
        *(uint32_t*)&g_a16[m1r + col] = packh2(oacc[j][2] * inv1, oacc[j][3] * inv1);
    }
}

// ---------------------------------------------------------------------------
extern "C" void kernel_launch(void* const* d_in, const int* in_sizes, int n_in,
                              void* d_out, int out_size)
{
    const float* x  = (const float*)d_in[0];
    const float* Wq = (const float*)d_in[1];
    const float* bq = (const float*)d_in[2];
    const float* Wp = (const float*)d_in[3];
    const float* bp = (const float*)d_in[4];
    float* out = (float*)d_out;

    cudaFuncSetAttribute(hgemm_kernel,
                         cudaFuncAttributeMaxDynamicSharedMemorySize, GEMM_SMEM);
    cudaFuncSetAttribute(attn_kernel,
                         cudaFuncAttributeMaxDynamicSharedMemorySize, ATT_SMEM);

    conv_all_kernel<<<M_ + 768 + 256, 256>>>(x, Wq, Wp);

    hgemm_kernel<<<dim3(QKV_N / 128, M_ / 128), 160, GEMM_SMEM>>>(bq, out, 0);

    attn_kernel<<<dim3(N_ / 64, H_, B_), 128, ATT_SMEM>>>();

    hgemm_kernel<<<dim3(E_ / 128, M_ / 128), 160, GEMM_SMEM>>>(bp, out, 1);
}

// round 16
// speedup vs baseline: 1.2828x; 1.0049x over previous
#include <cuda_runtime.h>
#include <cuda_fp16.h>
#include <cstdint>

#define B_   16
#define N_   1024
#define E_   1024
#define H_   16
#define D_   64
#define M_   (B_ * N_)        // 16384
#define QKV_N (3 * E_)        // 3072
#define KT_   (E_ / 64)       // 16 k-iters of 64

// ---------------------------------------------------------------------------
// Scratch (__device__ globals; no allocations)
// ---------------------------------------------------------------------------
static __device__ __align__(1024) __half g_q16 [(size_t)B_ * H_ * N_ * D_];
static __device__ __align__(1024) __half g_k16 [(size_t)B_ * H_ * N_ * D_];
static __device__ __align__(1024) __half g_vt16[(size_t)B_ * H_ * D_ * N_];  // V^T [B,H,D,N]
static __device__ __align__(1024) __half g_a16 [(size_t)M_ * E_];    // x, then attn out
static __device__ __align__(1024) __half g_wq16[(size_t)QKV_N * E_]; // Wqkv^T (n-major)
static __device__ __align__(1024) __half g_wp16[(size_t)E_ * E_];    // Wproj^T (n-major)

// ---------------------------------------------------------------------------
// helpers
// ---------------------------------------------------------------------------
__device__ __forceinline__ uint32_t smem_u32(const void* p) {
    uint32_t a;
    asm("{ .reg .u64 t; cvta.to.shared.u64 t, %1; cvt.u32.u64 %0, t; }"
        : "=r"(a) : "l"(p));
    return a;
}
__device__ __forceinline__ void cp_async16(uint32_t dst, const void* src) {
    asm volatile("cp.async.cg.shared.global [%0], [%1], 16;" :: "r"(dst), "l"(src));
}
__device__ __forceinline__ void cp_commit() {
    asm volatile("cp.async.commit_group;" ::: "memory");
}
__device__ __forceinline__ void ldmatrix_x4(uint32_t* d, uint32_t addr) {
    asm volatile("ldmatrix.sync.aligned.m8n8.x4.shared.b16 {%0,%1,%2,%3}, [%4];"
                 : "=r"(d[0]), "=r"(d[1]), "=r"(d[2]), "=r"(d[3]) : "r"(addr));
}
__device__ __forceinline__ void mma16816(float* c, const uint32_t* a,
                                         uint32_t b0, uint32_t b1) {
    asm volatile(
        "mma.sync.aligned.m16n8k16.row.col.f32.f16.f16.f32 "
        "{%0,%1,%2,%3}, {%4,%5,%6,%7}, {%8,%9}, {%0,%1,%2,%3};"
        : "+f"(c[0]), "+f"(c[1]), "+f"(c[2]), "+f"(c[3])
        : "r"(a[0]), "r"(a[1]), "r"(a[2]), "r"(a[3]), "r"(b0), "r"(b1));
}
__device__ __forceinline__ uint32_t packh2(float x, float y) {
    __half2 h = __floats2half2_rn(x, y);
    return *reinterpret_cast<uint32_t*>(&h);
}
__device__ __forceinline__ float ex2(float x) {
    float y;
    asm("ex2.approx.f32 %0, %1;" : "=f"(y) : "f"(x));
    return y;
}
#define MBAR_INIT(addr, cnt) \
    asm volatile("mbarrier.init.shared.b64 [%0], %1;" :: "r"(addr), "r"(cnt) : "memory")
#define MBAR_ARRIVE(addr) \
    asm volatile("mbarrier.arrive.shared.b64 _, [%0];" :: "r"(addr) : "memory")
#define MBAR_ARRIVE_CPASYNC(addr) \
    asm volatile("cp.async.mbarrier.arrive.noinc.shared.b64 [%0];" :: "r"(addr) : "memory")
#define MBAR_WAIT(addr, parity) do {                                          \
    asm volatile(                                                             \
        "{\n\t.reg .pred P1;\n\t"                                             \
        "WAIT_%=:\n\t"                                                        \
        "mbarrier.try_wait.parity.acquire.cta.shared::cta.b64 P1, [%0], %1, 0x989680;\n\t" \
        "@P1 bra.uni DONE_%=;\n\t"                                            \
        "bra.uni WAIT_%=;\n\t"                                                \
        "DONE_%=:\n\t}"                                                       \
        :: "r"(addr), "r"(parity) : "memory");                                \
} while (0)

// ---------------------------------------------------------------------------
// Fused conversion kernel (single launch):
//   blocks [0, 8192)        : x fp32 -> g_a16 fp16 (2 rows/block, 8 elem/thr)
//   blocks [8192, 8192+768) : Wq transpose tiles (16 kblk x 48 nblk)
//   blocks [+768, +256)     : Wp transpose tiles (16 kblk x 16 nblk)
// ---------------------------------------------------------------------------
#define XBLK (M_ / 2)   // 8192

__global__ __launch_bounds__(256) void conv_all_kernel(
    const float* __restrict__ x, const float* __restrict__ Wq,
    const float* __restrict__ Wp)
{
    __shared__ float tile[64][65];
    const int tid = threadIdx.x;
    const int bidx = blockIdx.x;

    if (bidx < XBLK) {
        // 2 rows per block; thread handles 8 consecutive elements
        const int m  = bidx * 2 + (tid >> 7);
        const int k8 = (tid & 127) << 3;
        const float* src = x + (size_t)m * E_ + k8;
        float4 v0 = *(const float4*)(src);
        float4 v1 = *(const float4*)(src + 4);
        uint4 o;
        o.x = packh2(v0.x, v0.y);
        o.y = packh2(v0.z, v0.w);
        o.z = packh2(v1.x, v1.y);
        o.w = packh2(v1.z, v1.w);
        *(uint4*)&g_a16[(size_t)m * E_ + k8] = o;
        return;
    }

    const float* W;
    __half* dst;
    int Ncols, t;
    if (bidx < XBLK + 768) {
        t = bidx - XBLK;       W = Wq; dst = g_wq16; Ncols = QKV_N;
    } else {
        t = bidx - XBLK - 768; W = Wp; dst = g_wp16; Ncols = E_;
    }
    const int k0 = (t & 15) * 64;
    const int n0 = (t >> 4) * 64;

    const int lr = tid >> 6;
    const int lc = tid & 63;
#pragma unroll
    for (int i = 0; i < 16; i++) {
        const int r = lr + i * 4;
        tile[r][lc] = W[(size_t)(k0 + r) * Ncols + n0 + lc];
    }
    __syncthreads();

    const int nl = tid >> 2;
    const int kc = (tid & 3) << 4;
#pragma unroll
    for (int j = 0; j < 16; j += 4) {
        uint2 o;
        o.x = packh2(tile[kc + j][nl],     tile[kc + j + 1][nl]);
        o.y = packh2(tile[kc + j + 2][nl], tile[kc + j + 3][nl]);
        *(uint2*)&dst[(size_t)(n0 + nl) * E_ + k0 + kc + j] = o;
    }
}

// ---------------------------------------------------------------------------
// fp16 HMMA GEMM — round-13 best (160 threads: 4 consumer warps 64x64 +
// 1 producer warp), __launch_bounds__(160, 2) pins 2 CTA/SM.
// 3-stage ring, stage 32KB (A @0, B @16384), barriers @0..47, stages @1024.
// mode 0: write Q/K fp16 [B,H,N,D] + V^T fp16 [B,H,D,N]; mode 1: fp32 out.
// ---------------------------------------------------------------------------
#define GEMM_SMEM (1024 + 3 * 32768)

__global__ __launch_bounds__(160, 2) void hgemm_kernel(
    const float* __restrict__ bias, float* __restrict__ out, int mode)
{
    extern __shared__ char smem[];
    const uint32_t sb = smem_u32(smem);
    const __half* A  = g_a16;
    const __half* Bt = (mode == 0) ? g_wq16 : g_wp16;

    const int tid  = threadIdx.x;
    const int lane = tid & 31, wid = tid >> 5;
    const int m0 = blockIdx.y * 128, n0 = blockIdx.x * 128;

    if (tid == 0) {
#pragma unroll
        for (int s = 0; s < 3; s++) {
            MBAR_INIT(sb + s * 16, 32);       // full: 32 producer threads
            MBAR_INIT(sb + s * 16 + 8, 128);  // empty: 128 consumer threads
        }
    }
    __syncthreads();   // the ONLY block-wide barrier

    if (wid == 4) {
        // ------------------------- producer warp -------------------------
        const char* aBase = (const char*)(A  + (size_t)m0 * E_);
        const char* bBase = (const char*)(Bt + (size_t)n0 * E_);
        for (int t = 0; t < KT_; t++) {
            const int s = t % 3;
            if (t >= 3) MBAR_WAIT(sb + s * 16 + 8, ((t - 3) / 3) & 1);
            const uint32_t sa = sb + 1024 + s * 32768;
            const char* aSrc = aBase + t * 128;
            const char* bSrc = bBase + t * 128;
#pragma unroll
            for (int i = 0; i < 32; i++) {
                const int u = i * 32 + lane;
                const int r = u >> 3, c = u & 7;
                cp_async16(sa + r * 128 + ((c ^ (r & 7)) << 4),
                           aSrc + (size_t)r * (E_ * 2) + c * 16);
            }
#pragma unroll
            for (int i = 0; i < 32; i++) {
                const int u = i * 32 + lane;
                const int r = u >> 3, c = u & 7;
                cp_async16(sa + 16384 + r * 128 + ((c ^ (r & 7)) << 4),
                           bSrc + (size_t)r * (E_ * 2) + c * 16);
            }
            MBAR_ARRIVE_CPASYNC(sb + s * 16);
        }
        return;
    }

    // --------------------------- consumer warps ---------------------------
    const int warp_m = wid & 1, warp_n = wid >> 1;

    float acc[4][8][4];
#pragma unroll
    for (int i = 0; i < 4; i++)
#pragma unroll
        for (int j = 0; j < 8; j++)
#pragma unroll
            for (int r = 0; r < 4; r++) acc[i][j][r] = 0.f;

    const int lane15 = lane & 15, lhalf = lane >> 4;
    const int ra  = warp_m * 64 + lane15;
    const int rbw = warp_n * 64 + lane15;

    for (int kt = 0; kt < KT_; kt++) {
        const int s = kt % 3;
        MBAR_WAIT(sb + s * 16, (kt / 3) & 1);   // full[s]

        const uint32_t sa  = sb + 1024 + s * 32768;
        const uint32_t sbB = sa + 16384;

        uint32_t afr[2][4][4], bfr[2][4][4];
        {
            const int kc = lhalf;
#pragma unroll
            for (int mi = 0; mi < 4; mi++) {
                const int r = ra + mi * 16;
                ldmatrix_x4(afr[0][mi], sa + r * 128 + ((kc ^ (r & 7)) << 4));
            }
#pragma unroll
            for (int ng = 0; ng < 4; ng++) {
                const int r = rbw + ng * 16;
                ldmatrix_x4(bfr[0][ng], sbB + r * 128 + ((kc ^ (r & 7)) << 4));
            }
        }
#pragma unroll
        for (int kk = 0; kk < 4; kk++) {
            const int cur = kk & 1, nxt = cur ^ 1;
            if (kk < 3) {
                const int kc = (kk + 1) * 2 + lhalf;
#pragma unroll
                for (int mi = 0; mi < 4; mi++) {
                    const int r = ra + mi * 16;
                    ldmatrix_x4(afr[nxt][mi], sa + r * 128 + ((kc ^ (r & 7)) << 4));
                }
#pragma unroll
                for (int ng = 0; ng < 4; ng++) {
                    const int r = rbw + ng * 16;
                    ldmatrix_x4(bfr[nxt][ng], sbB + r * 128 + ((kc ^ (r & 7)) << 4));
                }
            }
#pragma unroll
            for (int mi = 0; mi < 4; mi++)
#pragma unroll
                for (int nj = 0; nj < 8; nj++)
                    mma16816(acc[mi][nj], afr[cur][mi],
                             bfr[cur][nj >> 1][nj & 1],
                             bfr[cur][nj >> 1][(nj & 1) + 2]);
        }
        MBAR_ARRIVE(sb + s * 16 + 8);           // empty[s]
    }

    // Epilogue (consumers only)
    const int mrow = m0 + warp_m * 64 + (lane >> 2);
    const int ncb  = n0 + warp_n * 64 + (lane & 3) * 2;
#pragma unroll
    for (int mi = 0; mi < 4; mi++) {
#pragma unroll
        for (int nj = 0; nj < 8; nj++) {
            const int c  = ncb + nj * 8;
            const float b0 = bias[c], b1 = bias[c + 1];
            const int r0 = mrow + mi * 16;
            const float v00 = acc[mi][nj][0] + b0, v01 = acc[mi][nj][1] + b1;
            const float v10 = acc[mi][nj][2] + b0, v11 = acc[mi][nj][3] + b1;
            if (mode == 1) {
                float2 p0; p0.x = v00; p0.y = v01;
                float2 p1; p1.x = v10; p1.y = v11;
                *(float2*)&out[(size_t)r0 * E_ + c] = p0;
                *(float2*)&out[(size_t)(r0 + 8) * E_ + c] = p1;
                continue;
            }
            const int sec = c >> 10, e = c & 1023;
            const int hh = e >> 6, dd = e & 63;
            const int bb = r0 >> 10, nn = r0 & 1023;
            if (sec <= 1) {
                __half* dq = sec == 0 ? g_q16 : g_k16;
                const size_t i0 = (((size_t)bb * H_ + hh) * N_ + nn) * D_ + dd;
                *(uint32_t*)&dq[i0]          = packh2(v00, v01);
                *(uint32_t*)&dq[i0 + 8 * D_] = packh2(v10, v11);
            } else {
                const size_t i00 = (((size_t)bb * H_ + hh) * D_ + dd) * N_ + nn;
                g_vt16[i00]          = __float2half_rn(v00);
                g_vt16[i00 + N_]     = __float2half_rn(v01);
                g_vt16[i00 + 8]      = __float2half_rn(v10);
                g_vt16[i00 + N_ + 8] = __float2half_rn(v11);
            }
        }
    }
}

// ---------------------------------------------------------------------------
// Flash attention, fp16 HMMA — 64 q-rows per CTA, 128 threads (4 warps),
// 2-stage cp.async pipeline. __launch_bounds__(128, 3) -> THREE CTAs/SM
// (regs 128*170*3 = 65280 <= 64K regfile... 170-cap; smem 3*32KB = 96KB of
// 228KB) so co-resident CTAs' MMAs cover this CTA's softmax phases.
// stage: K @0 (8KB), V^T @8192 (8KB); stride 16384; total 32KB.
// ---------------------------------------------------------------------------
#define ATT_SMEM (2 * 16384)

__device__ __forceinline__ void att_load_tile(
    uint32_t st, int kv0, const __half* k16, const __half* vt16, int tid)
{
#pragma unroll
    for (int i = 0; i < 4; i++) {
        const int u = i * 128 + tid;
        const int r = u >> 3, c = u & 7;
        const uint32_t soff = r * 128 + ((c ^ (r & 7)) << 4);
        cp_async16(st + soff,        (const char*)k16  + (size_t)(kv0 + r) * 128 + c * 16);
        cp_async16(st + 8192 + soff, (const char*)vt16 + (size_t)r * 2048 + kv0 * 2 + c * 16);
    }
    cp_commit();
}

__global__ __launch_bounds__(128, 3) void attn_kernel()
{
    extern __shared__ char smem[];
    const uint32_t sb = smem_u32(smem);

    const int tid = threadIdx.x;
    const int lane = tid & 31, w = tid >> 5;
    const int lane15 = lane & 15, lhalf = lane >> 4;
    const int q0 = blockIdx.x * 64;
    const int h  = blockIdx.y;
    const int b  = blockIdx.z;

    const size_t hb = (size_t)(b * H_ + h) * (N_ * D_);
    const __half* q16  = g_q16  + hb;
    const __half* k16  = g_k16  + hb;
    const __half* vt16 = g_vt16 + hb;

    // stage Q in stage-0 K region, extract fragments
#pragma unroll
    for (int i = 0; i < 4; i++) {
        const int u = i * 128 + tid;
        const int r = u >> 3, c = u & 7;
        cp_async16(sb + r * 128 + ((c ^ (r & 7)) << 4),
                   (const char*)q16 + (size_t)(q0 + r) * 128 + c * 16);
    }
    cp_commit();
    asm volatile("cp.async.wait_group 0;" ::: "memory");
    __syncthreads();

    uint32_t qf[4][4];
    {
        const int r = w * 16 + lane15;
#pragma unroll
        for (int t = 0; t < 4; t++)
            ldmatrix_x4(qf[t], sb + r * 128 + (((t * 2 + lhalf) ^ (r & 7)) << 4));
    }
    __syncthreads();

    float mstate[2] = {-1e30f, -1e30f};
    float lstate[2] = {0.f, 0.f};
    float oacc[8][4];
#pragma unroll
    for (int j = 0; j < 8; j++)
#pragma unroll
        for (int r = 0; r < 4; r++) oacc[j][r] = 0.f;

    const float cexp = 0.18033688f;   // D^-0.5 * log2(e)

    att_load_tile(sb, 0, k16, vt16, tid);
    att_load_tile(sb + 16384, 64, k16, vt16, tid);

    for (int t = 0; t < 16; t++) {
        asm volatile("cp.async.wait_group 1;" ::: "memory");
        __syncthreads();
        const uint32_t stK = sb + (t & 1) * 16384;
        const uint32_t stV = stK + 8192;

        float sacc[8][4];
#pragma unroll
        for (int j = 0; j < 8; j++)
#pragma unroll
            for (int r = 0; r < 4; r++) sacc[j][r] = 0.f;

#pragma unroll
        for (int kvg = 0; kvg < 4; kvg++) {
            const int rb = kvg * 16 + lane15;
#pragma unroll
            for (int kk = 0; kk < 4; kk++) {
                uint32_t bf[4];
                ldmatrix_x4(bf, stK + rb * 128 + (((kk * 2 + lhalf) ^ (rb & 7)) << 4));
                mma16816(sacc[2 * kvg],     qf[kk], bf[0], bf[2]);
                mma16816(sacc[2 * kvg + 1], qf[kk], bf[1], bf[3]);
            }
        }

#pragma unroll
        for (int rr = 0; rr < 2; rr++) {
            float mx = -1e30f;
#pragma unroll
            for (int j = 0; j < 8; j++)
                mx = fmaxf(mx, fmaxf(sacc[j][rr * 2], sacc[j][rr * 2 + 1]));
            mx = fmaxf(mx, __shfl_xor_sync(0xffffffffu, mx, 1));
            mx = fmaxf(mx, __shfl_xor_sync(0xffffffffu, mx, 2));
            const float mnew  = fmaxf(mstate[rr], mx);
            const float alpha = ex2((mstate[rr] - mnew) * cexp);
            mstate[rr] = mnew;
            float rs = 0.f;
#pragma unroll
            for (int j = 0; j < 8; j++) {
                const float p0 = ex2((sacc[j][rr * 2]     - mnew) * cexp);
                const float p1 = ex2((sacc[j][rr * 2 + 1] - mnew) * cexp);
                sacc[j][rr * 2] = p0; sacc[j][rr * 2 + 1] = p1;
                rs += p0 + p1;
            }
            rs += __shfl_xor_sync(0xffffffffu, rs, 1);
            rs += __shfl_xor_sync(0xffffffffu, rs, 2);
            lstate[rr] = lstate[rr] * alpha + rs;
#pragma unroll
            for (int j = 0; j < 8; j++) {
                oacc[j][rr * 2]     *= alpha;
                oacc[j][rr * 2 + 1] *= alpha;
            }
        }

        // P fragments in registers (C-frag layout == A-frag layout)
        uint32_t pf[4][4];
#pragma unroll
        for (int kk = 0; kk < 4; kk++) {
#pragma unroll
            for (int q = 0; q < 4; q++) {
                const int tile = 2 * kk + (q >> 1);
                const int ri   = (q & 1) * 2;
                pf[kk][q] = packh2(sacc[tile][ri], sacc[tile][ri + 1]);
            }
        }

#pragma unroll
        for (int dg = 0; dg < 4; dg++) {
            const int rb = dg * 16 + lane15;
#pragma unroll
            for (int kk = 0; kk < 4; kk++) {
                uint32_t bf[4];
                ldmatrix_x4(bf, stV + rb * 128 + (((kk * 2 + lhalf) ^ (rb & 7)) << 4));
                mma16816(oacc[2 * dg],     pf[kk], bf[0], bf[2]);
                mma16816(oacc[2 * dg + 1], pf[kk], bf[1], bf[3]);
            }
        }

        __syncthreads();
        if (t + 2 < 16)
            att_load_tile(sb + (t & 1) * 16384, (t + 2) * 64, k16, vt16, tid);
        else
            cp_commit();
    }

    // epilogue: normalize, write fp16 O rows into g_a16 [M, E]
    const float inv0 = 1.f / lstate[0];
    const float inv1 = 1.f / lstate[1];
    const int qrow = q0 + w * 16 + (lane >> 2);
    const size_t m0r = (size_t)(b * N_ + qrow) * E_;
    const size_t m1r = m0r + (size_t)8 * E_;
    const int colb = h * 64 + 2 * (lane & 3);
#pragma unroll
    for (int j = 0; j < 8; j++) {
        const int col = colb + 8 * j;
        *(uint32_t*)&g_a16[m0r + col] = packh2(oacc[j][0] * inv0, oacc[j][1] * inv0);
        *(uint32_t*)&g_a16[m1r + col] = packh2(oacc[j][2] * inv1, oacc[j][3] * inv1);
    }
}

// ---------------------------------------------------------------------------
extern "C" void kernel_launch(void* const* d_in, const int* in_sizes, int n_in,
                              void* d_out, int out_size)
{
    const float* x  = (const float*)d_in[0];
    const float* Wq = (const float*)d_in[1];
    const float* bq = (const float*)d_in[2];
    const float* Wp = (const float*)d_in[3];
    const float* bp = (const float*)d_in[4];
    float* out = (float*)d_out;

    cudaFuncSetAttribute(hgemm_kernel,
                         cudaFuncAttributeMaxDynamicSharedMemorySize, GEMM_SMEM);
    cudaFuncSetAttribute(attn_kernel,
                         cudaFuncAttributeMaxDynamicSharedMemorySize, ATT_SMEM);

    conv_all_kernel<<<XBLK + 768 + 256, 256>>>(x, Wq, Wp);

    hgemm_kernel<<<dim3(QKV_N / 128, M_ / 128), 160, GEMM_SMEM>>>(bq, out, 0);

    attn_kernel<<<dim3(N_ / 64, H_, B_), 128, ATT_SMEM>>>();

    hgemm_kernel<<<dim3(E_ / 128, M_ / 128), 160, GEMM_SMEM>>>(bp, out, 1);
}

// round 17
// speedup vs baseline: 1.2875x; 1.0037x over previous
#include <cuda_runtime.h>
#include <cuda_fp16.h>
#include <cstdint>

#define B_   16
#define N_   1024
#define E_   1024
#define H_   16
#define D_   64
#define M_   (B_ * N_)        // 16384
#define QKV_N (3 * E_)        // 3072
#define KT_   (E_ / 64)       // 16 k-iters of 64

// ---------------------------------------------------------------------------
// Scratch (__device__ globals; no allocations)
// ---------------------------------------------------------------------------
static __device__ __align__(1024) __half g_q16 [(size_t)B_ * H_ * N_ * D_];
static __device__ __align__(1024) __half g_k16 [(size_t)B_ * H_ * N_ * D_];
static __device__ __align__(1024) __half g_vt16[(size_t)B_ * H_ * D_ * N_];  // V^T [B,H,D,N]
static __device__ __align__(1024) __half g_a16 [(size_t)M_ * E_];    // x, then attn out
static __device__ __align__(1024) __half g_wq16[(size_t)QKV_N * E_]; // Wqkv^T (n-major)
static __device__ __align__(1024) __half g_wp16[(size_t)E_ * E_];    // Wproj^T (n-major)

// ---------------------------------------------------------------------------
// helpers
// ---------------------------------------------------------------------------
__device__ __forceinline__ uint32_t smem_u32(const void* p) {
    uint32_t a;
    asm("{ .reg .u64 t; cvta.to.shared.u64 t, %1; cvt.u32.u64 %0, t; }"
        : "=r"(a) : "l"(p));
    return a;
}
__device__ __forceinline__ void cp_async16(uint32_t dst, const void* src) {
    asm volatile("cp.async.cg.shared.global [%0], [%1], 16;" :: "r"(dst), "l"(src));
}
__device__ __forceinline__ void cp_commit() {
    asm volatile("cp.async.commit_group;" ::: "memory");
}
__device__ __forceinline__ void ldmatrix_x4(uint32_t* d, uint32_t addr) {
    asm volatile("ldmatrix.sync.aligned.m8n8.x4.shared.b16 {%0,%1,%2,%3}, [%4];"
                 : "=r"(d[0]), "=r"(d[1]), "=r"(d[2]), "=r"(d[3]) : "r"(addr));
}
__device__ __forceinline__ void mma16816(float* c, const uint32_t* a,
                                         uint32_t b0, uint32_t b1) {
    asm volatile(
        "mma.sync.aligned.m16n8k16.row.col.f32.f16.f16.f32 "
        "{%0,%1,%2,%3}, {%4,%5,%6,%7}, {%8,%9}, {%0,%1,%2,%3};"
        : "+f"(c[0]), "+f"(c[1]), "+f"(c[2]), "+f"(c[3])
        : "r"(a[0]), "r"(a[1]), "r"(a[2]), "r"(a[3]), "r"(b0), "r"(b1));
}
__device__ __forceinline__ uint32_t packh2(float x, float y) {
    __half2 h = __floats2half2_rn(x, y);
    return *reinterpret_cast<uint32_t*>(&h);
}
__device__ __forceinline__ float ex2(float x) {
    float y;
    asm("ex2.approx.f32 %0, %1;" : "=f"(y) : "f"(x));
    return y;
}
#define MBAR_INIT(addr, cnt) \
    asm volatile("mbarrier.init.shared.b64 [%0], %1;" :: "r"(addr), "r"(cnt) : "memory")
#define MBAR_ARRIVE(addr) \
    asm volatile("mbarrier.arrive.shared.b64 _, [%0];" :: "r"(addr) : "memory")
#define MBAR_ARRIVE_CPASYNC(addr) \
    asm volatile("cp.async.mbarrier.arrive.noinc.shared.b64 [%0];" :: "r"(addr) : "memory")
#define MBAR_WAIT(addr, parity) do {                                          \
    asm volatile(                                                             \
        "{\n\t.reg .pred P1;\n\t"                                             \
        "WAIT_%=:\n\t"                                                        \
        "mbarrier.try_wait.parity.acquire.cta.shared::cta.b64 P1, [%0], %1, 0x989680;\n\t" \
        "@P1 bra.uni DONE_%=;\n\t"                                            \
        "bra.uni WAIT_%=;\n\t"                                                \
        "DONE_%=:\n\t}"                                                       \
        :: "r"(addr), "r"(parity) : "memory");                                \
} while (0)

// ---------------------------------------------------------------------------
// Fused conversion kernel (single launch). W tiles first (fewer blocks,
// finish early), then x rows (2 rows/block, 8 elem/thread).
//   blocks [0, 768)        : Wq transpose tiles (16 kblk x 48 nblk)
//   blocks [768, 1024)     : Wp transpose tiles (16 kblk x 16 nblk)
//   blocks [1024, 1024+8192): x fp32 -> g_a16 fp16
// ---------------------------------------------------------------------------
#define XBLK (M_ / 2)   // 8192

__global__ __launch_bounds__(256) void conv_all_kernel(
    const float* __restrict__ x, const float* __restrict__ Wq,
    const float* __restrict__ Wp)
{
    __shared__ float tile[64][65];
    const int tid = threadIdx.x;
    const int bidx = blockIdx.x;

    if (bidx >= 1024) {
        const int bx = bidx - 1024;
        const int m  = bx * 2 + (tid >> 7);
        const int k8 = (tid & 127) << 3;
        const float* src = x + (size_t)m * E_ + k8;
        float4 v0 = *(const float4*)(src);
        float4 v1 = *(const float4*)(src + 4);
        uint4 o;
        o.x = packh2(v0.x, v0.y);
        o.y = packh2(v0.z, v0.w);
        o.z = packh2(v1.x, v1.y);
        o.w = packh2(v1.z, v1.w);
        *(uint4*)&g_a16[(size_t)m * E_ + k8] = o;
        return;
    }

    const float* W;
    __half* dst;
    int Ncols, t;
    if (bidx < 768) {
        t = bidx;       W = Wq; dst = g_wq16; Ncols = QKV_N;
    } else {
        t = bidx - 768; W = Wp; dst = g_wp16; Ncols = E_;
    }
    const int k0 = (t & 15) * 64;
    const int n0 = (t >> 4) * 64;

    const int lr = tid >> 6;
    const int lc = tid & 63;
#pragma unroll
    for (int i = 0; i < 16; i++) {
        const int r = lr + i * 4;
        tile[r][lc] = W[(size_t)(k0 + r) * Ncols + n0 + lc];
    }
    __syncthreads();

    const int nl = tid >> 2;
    const int kc = (tid & 3) << 4;
#pragma unroll
    for (int j = 0; j < 16; j += 4) {
        uint2 o;
        o.x = packh2(tile[kc + j][nl],     tile[kc + j + 1][nl]);
        o.y = packh2(tile[kc + j + 2][nl], tile[kc + j + 3][nl]);
        *(uint2*)&dst[(size_t)(n0 + nl) * E_ + k0 + kc + j] = o;
    }
}

// ---------------------------------------------------------------------------
// fp16 HMMA GEMM — round-13 best (160 threads: 4 consumer warps 64x64 +
// 1 producer warp), __launch_bounds__(160, 2) pins 2 CTA/SM.
// 3-stage ring, stage 32KB (A @0, B @16384), barriers @0..47, stages @1024.
// mode 0: write Q/K fp16 [B,H,N,D] + V^T fp16 [B,H,D,N]; mode 1: fp32 out.
// ---------------------------------------------------------------------------
#define GEMM_SMEM (1024 + 3 * 32768)

__global__ __launch_bounds__(160, 2) void hgemm_kernel(
    const float* __restrict__ bias, float* __restrict__ out, int mode)
{
    extern __shared__ char smem[];
    const uint32_t sb = smem_u32(smem);
    const __half* A  = g_a16;
    const __half* Bt = (mode == 0) ? g_wq16 : g_wp16;

    const int tid  = threadIdx.x;
    const int lane = tid & 31, wid = tid >> 5;
    const int m0 = blockIdx.y * 128, n0 = blockIdx.x * 128;

    if (tid == 0) {
#pragma unroll
        for (int s = 0; s < 3; s++) {
            MBAR_INIT(sb + s * 16, 32);       // full: 32 producer threads
            MBAR_INIT(sb + s * 16 + 8, 128);  // empty: 128 consumer threads
        }
    }
    __syncthreads();   // the ONLY block-wide barrier

    if (wid == 4) {
        // ------------------------- producer warp -------------------------
        const char* aBase = (const char*)(A  + (size_t)m0 * E_);
        const char* bBase = (const char*)(Bt + (size_t)n0 * E_);
        for (int t = 0; t < KT_; t++) {
            const int s = t % 3;
            if (t >= 3) MBAR_WAIT(sb + s * 16 + 8, ((t - 3) / 3) & 1);
            const uint32_t sa = sb + 1024 + s * 32768;
            const char* aSrc = aBase + t * 128;
            const char* bSrc = bBase + t * 128;
#pragma unroll
            for (int i = 0; i < 32; i++) {
                const int u = i * 32 + lane;
                const int r = u >> 3, c = u & 7;
                cp_async16(sa + r * 128 + ((c ^ (r & 7)) << 4),
                           aSrc + (size_t)r * (E_ * 2) + c * 16);
            }
#pragma unroll
            for (int i = 0; i < 32; i++) {
                const int u = i * 32 + lane;
                const int r = u >> 3, c = u & 7;
                cp_async16(sa + 16384 + r * 128 + ((c ^ (r & 7)) << 4),
                           bSrc + (size_t)r * (E_ * 2) + c * 16);
            }
            MBAR_ARRIVE_CPASYNC(sb + s * 16);
        }
        return;
    }

    // --------------------------- consumer warps ---------------------------
    const int warp_m = wid & 1, warp_n = wid >> 1;

    float acc[4][8][4];
#pragma unroll
    for (int i = 0; i < 4; i++)
#pragma unroll
        for (int j = 0; j < 8; j++)
#pragma unroll
            for (int r = 0; r < 4; r++) acc[i][j][r] = 0.f;

    const int lane15 = lane & 15, lhalf = lane >> 4;
    const int ra  = warp_m * 64 + lane15;
    const int rbw = warp_n * 64 + lane15;

    for (int kt = 0; kt < KT_; kt++) {
        const int s = kt % 3;
        MBAR_WAIT(sb + s * 16, (kt / 3) & 1);   // full[s]

        const uint32_t sa  = sb + 1024 + s * 32768;
        const uint32_t sbB = sa + 16384;

        uint32_t afr[2][4][4], bfr[2][4][4];
        {
            const int kc = lhalf;
#pragma unroll
            for (int mi = 0; mi < 4; mi++) {
                const int r = ra + mi * 16;
                ldmatrix_x4(afr[0][mi], sa + r * 128 + ((kc ^ (r & 7)) << 4));
            }
#pragma unroll
            for (int ng = 0; ng < 4; ng++) {
                const int r = rbw + ng * 16;
                ldmatrix_x4(bfr[0][ng], sbB + r * 128 + ((kc ^ (r & 7)) << 4));
            }
        }
#pragma unroll
        for (int kk = 0; kk < 4; kk++) {
            const int cur = kk & 1, nxt = cur ^ 1;
            if (kk < 3) {
                const int kc = (kk + 1) * 2 + lhalf;
#pragma unroll
                for (int mi = 0; mi < 4; mi++) {
                    const int r = ra + mi * 16;
                    ldmatrix_x4(afr[nxt][mi], sa + r * 128 + ((kc ^ (r & 7)) << 4));
                }
#pragma unroll
                for (int ng = 0; ng < 4; ng++) {
                    const int r = rbw + ng * 16;
                    ldmatrix_x4(bfr[nxt][ng], sbB + r * 128 + ((kc ^ (r & 7)) << 4));
                }
            }
#pragma unroll
            for (int mi = 0; mi < 4; mi++)
#pragma unroll
                for (int nj = 0; nj < 8; nj++)
                    mma16816(acc[mi][nj], afr[cur][mi],
                             bfr[cur][nj >> 1][nj & 1],
                             bfr[cur][nj >> 1][(nj & 1) + 2]);
        }
        MBAR_ARRIVE(sb + s * 16 + 8);           // empty[s]
    }

    // Epilogue (consumers only)
    const int mrow = m0 + warp_m * 64 + (lane >> 2);
    const int ncb  = n0 + warp_n * 64 + (lane & 3) * 2;
#pragma unroll
    for (int mi = 0; mi < 4; mi++) {
#pragma unroll
        for (int nj = 0; nj < 8; nj++) {
            const int c  = ncb + nj * 8;
            const float b0 = bias[c], b1 = bias[c + 1];
            const int r0 = mrow + mi * 16;
            const float v00 = acc[mi][nj][0] + b0, v01 = acc[mi][nj][1] + b1;
            const float v10 = acc[mi][nj][2] + b0, v11 = acc[mi][nj][3] + b1;
            if (mode == 1) {
                float2 p0; p0.x = v00; p0.y = v01;
                float2 p1; p1.x = v10; p1.y = v11;
                *(float2*)&out[(size_t)r0 * E_ + c] = p0;
                *(float2*)&out[(size_t)(r0 + 8) * E_ + c] = p1;
                continue;
            }
            const int sec = c >> 10, e = c & 1023;
            const int hh = e >> 6, dd = e & 63;
            const int bb = r0 >> 10, nn = r0 & 1023;
            if (sec <= 1) {
                __half* dq = sec == 0 ? g_q16 : g_k16;
                const size_t i0 = (((size_t)bb * H_ + hh) * N_ + nn) * D_ + dd;
                *(uint32_t*)&dq[i0]          = packh2(v00, v01);
                *(uint32_t*)&dq[i0 + 8 * D_] = packh2(v10, v11);
            } else {
                const size_t i00 = (((size_t)bb * H_ + hh) * D_ + dd) * N_ + nn;
                g_vt16[i00]          = __float2half_rn(v00);
                g_vt16[i00 + N_]     = __float2half_rn(v01);
                g_vt16[i00 + 8]      = __float2half_rn(v10);
                g_vt16[i00 + N_ + 8] = __float2half_rn(v11);
            }
        }
    }
}

// ---------------------------------------------------------------------------
// Flash attention, fp16 HMMA — 64 q-rows per CTA, 128 threads (4 warps),
// __launch_bounds__(128, 3) -> 3 CTA/SM. THREE-stage K/V ring with ONE
// __syncthreads per kv-iter (wait -> sync -> issue t+2 -> compute); with 12
// warps/SM the freed barrier slack is actually fillable.
// Stage = 16KB (K @0, V^T @8192); stages at sb + s*16384 (48KB/CTA, 144KB/SM).
// ---------------------------------------------------------------------------
#define ATT_SMEM (3 * 16384)

__device__ __forceinline__ void att_load_tile(
    uint32_t st, int kv0, const __half* k16, const __half* vt16, int tid)
{
#pragma unroll
    for (int i = 0; i < 4; i++) {
        const int u = i * 128 + tid;
        const int r = u >> 3, c = u & 7;
        const uint32_t soff = r * 128 + ((c ^ (r & 7)) << 4);
        cp_async16(st + soff,        (const char*)k16  + (size_t)(kv0 + r) * 128 + c * 16);
        cp_async16(st + 8192 + soff, (const char*)vt16 + (size_t)r * 2048 + kv0 * 2 + c * 16);
    }
    cp_commit();
}

__global__ __launch_bounds__(128, 3) void attn_kernel()
{
    extern __shared__ char smem[];
    const uint32_t sb = smem_u32(smem);

    const int tid = threadIdx.x;
    const int lane = tid & 31, w = tid >> 5;
    const int lane15 = lane & 15, lhalf = lane >> 4;
    const int q0 = blockIdx.x * 64;
    const int h  = blockIdx.y;
    const int b  = blockIdx.z;

    const size_t hb = (size_t)(b * H_ + h) * (N_ * D_);
    const __half* q16  = g_q16  + hb;
    const __half* k16  = g_k16  + hb;
    const __half* vt16 = g_vt16 + hb;

    // stage Q in stage-0 region, extract fragments
#pragma unroll
    for (int i = 0; i < 4; i++) {
        const int u = i * 128 + tid;
        const int r = u >> 3, c = u & 7;
        cp_async16(sb + r * 128 + ((c ^ (r & 7)) << 4),
                   (const char*)q16 + (size_t)(q0 + r) * 128 + c * 16);
    }
    cp_commit();
    asm volatile("cp.async.wait_group 0;" ::: "memory");
    __syncthreads();

    uint32_t qf[4][4];
    {
        const int r = w * 16 + lane15;
#pragma unroll
        for (int t = 0; t < 4; t++)
            ldmatrix_x4(qf[t], sb + r * 128 + (((t * 2 + lhalf) ^ (r & 7)) << 4));
    }
    __syncthreads();

    float mstate[2] = {-1e30f, -1e30f};
    float lstate[2] = {0.f, 0.f};
    float oacc[8][4];
#pragma unroll
    for (int j = 0; j < 8; j++)
#pragma unroll
        for (int r = 0; r < 4; r++) oacc[j][r] = 0.f;

    const float cexp = 0.18033688f;   // D^-0.5 * log2(e)

    att_load_tile(sb, 0, k16, vt16, tid);
    att_load_tile(sb + 16384, 64, k16, vt16, tid);

    for (int t = 0; t < 16; t++) {
        asm volatile("cp.async.wait_group 1;" ::: "memory");
        __syncthreads();   // data-ready for t AND safe reuse of stage (t+2)%3
        if (t + 2 < 16)
            att_load_tile(sb + ((t + 2) % 3) * 16384, (t + 2) * 64, k16, vt16, tid);
        else
            cp_commit();   // keep group counting uniform

        const uint32_t stK = sb + (t % 3) * 16384;
        const uint32_t stV = stK + 8192;

        float sacc[8][4];
#pragma unroll
        for (int j = 0; j < 8; j++)
#pragma unroll
            for (int r = 0; r < 4; r++) sacc[j][r] = 0.f;

#pragma unroll
        for (int kvg = 0; kvg < 4; kvg++) {
            const int rb = kvg * 16 + lane15;
#pragma unroll
            for (int kk = 0; kk < 4; kk++) {
                uint32_t bf[4];
                ldmatrix_x4(bf, stK + rb * 128 + (((kk * 2 + lhalf) ^ (rb & 7)) << 4));
                mma16816(sacc[2 * kvg],     qf[kk], bf[0], bf[2]);
                mma16816(sacc[2 * kvg + 1], qf[kk], bf[1], bf[3]);
            }
        }

#pragma unroll
        for (int rr = 0; rr < 2; rr++) {
            float mx = -1e30f;
#pragma unroll
            for (int j = 0; j < 8; j++)
                mx = fmaxf(mx, fmaxf(sacc[j][rr * 2], sacc[j][rr * 2 + 1]));
            mx = fmaxf(mx, __shfl_xor_sync(0xffffffffu, mx, 1));
            mx = fmaxf(mx, __shfl_xor_sync(0xffffffffu, mx, 2));
            const float mnew  = fmaxf(mstate[rr], mx);
            const float alpha = ex2((mstate[rr] - mnew) * cexp);
            mstate[rr] = mnew;
            float rs = 0.f;
#pragma unroll
            for (int j = 0; j < 8; j++) {
                const float p0 = ex2((sacc[j][rr * 2]     - mnew) * cexp);
                const float p1 = ex2((sacc[j][rr * 2 + 1] - mnew) * cexp);
                sacc[j][rr * 2] = p0; sacc[j][rr * 2 + 1] = p1;
                rs += p0 + p1;
            }
            rs += __shfl_xor_sync(0xffffffffu, rs, 1);
            rs += __shfl_xor_sync(0xffffffffu, rs, 2);
            lstate[rr] = lstate[rr] * alpha + rs;
#pragma unroll
            for (int j = 0; j < 8; j++) {
                oacc[j][rr * 2]     *= alpha;
                oacc[j][rr * 2 + 1] *= alpha;
            }
        }

        // P fragments in registers (C-frag layout == A-frag layout)
        uint32_t pf[4][4];
#pragma unroll
        for (int kk = 0; kk < 4; kk++) {
#pragma unroll
            for (int q = 0; q < 4; q++) {
                const int tile = 2 * kk + (q >> 1);
                const int ri   = (q & 1) * 2;
                pf[kk][q] = packh2(sacc[tile][ri], sacc[tile][ri + 1]);
            }
        }

#pragma unroll
        for (int dg = 0; dg < 4; dg++) {
            const int rb = dg * 16 + lane15;
#pragma unroll
            for (int kk = 0; kk < 4; kk++) {
                uint32_t bf[4];
                ldmatrix_x4(bf, stV + rb * 128 + (((kk * 2 + lhalf) ^ (rb & 7)) << 4));
                mma16816(oacc[2 * dg],     pf[kk], bf[0], bf[2]);
                mma16816(oacc[2 * dg + 1], pf[kk], bf[1], bf[3]);
            }
        }
    }

    // epilogue: normalize, write fp16 O rows into g_a16 [M, E]
    const float inv0 = 1.f / lstate[0];
    const float inv1 = 1.f / lstate[1];
    const int qrow = q0 + w * 16 + (lane >> 2);
    const size_t m0r = (size_t)(b * N_ + qrow) * E_;
    const size_t m1r = m0r + (size_t)8 * E_;
    const int colb = h * 64 + 2 * (lane & 3);
#pragma unroll
    for (int j = 0; j < 8; j++) {
        const int col = colb + 8 * j;
        *(uint32_t*)&g_a16[m0r + col] = packh2(oacc[j][0] * inv0, oacc[j][1] * inv0);
        *(uint32_t*)&g_a16[m1r + col] = packh2(oacc[j][2] * inv1, oacc[j][3] * inv1);
    }
}

// ---------------------------------------------------------------------------
extern "C" void kernel_launch(void* const* d_in, const int* in_sizes, int n_in,
                              void* d_out, int out_size)
{
    const float* x  = (const float*)d_in[0];
    const float* Wq = (const float*)d_in[1];
    const float* bq = (const float*)d_in[2];
    const float* Wp = (const float*)d_in[3];
    const float* bp = (const float*)d_in[4];
    float* out = (float*)d_out;

    cudaFuncSetAttribute(hgemm_kernel,
                         cudaFuncAttributeMaxDynamicSharedMemorySize, GEMM_SMEM);
    cudaFuncSetAttribute(attn_kernel,
                         cudaFuncAttributeMaxDynamicSharedMemorySize, ATT_SMEM);

    conv_all_kernel<<<1024 + XBLK, 256>>>(x, Wq, Wp);

    hgemm_kernel<<<dim3(QKV_N / 128, M_ / 128), 160, GEMM_SMEM>>>(bq, out, 0);

    attn_kernel<<<dim3(N_ / 64, H_, B_), 128, ATT_SMEM>>>();

    hgemm_kernel<<<dim3(E_ / 128, M_ / 128), 160, GEMM_SMEM>>>(bp, out, 1);
}